// round 14
// baseline (speedup 1.0000x reference)
#include <cuda_runtime.h>
#include <cuda_bf16.h>
#include <cstdint>

// ---------------- problem constants ----------------
#define NN 50000
#define EE 800000
#define HH 64
#define RR 8
#define LL 3
#define LN_EPS 1e-5f
#define NEG_SLOPE 0.2f

// ---------------- device scratch ----------------
__device__ float g_h[2 * NN * HH];         // ping-pong node features
__device__ float g_prod[(size_t)NN * 512]; // relgemm output (normalized)
__device__ float g_gate[(size_t)NN * 512]; // gate pre-activation (raw)
__device__ float g_spre[(size_t)NN * 512]; // UNNORMALIZED ex-weighted h sums per (n,r)
__device__ float g_ap[NN * 16];            // attention projections
__device__ float g_denom[RR];
__device__ int g_deg[NN];
__device__ int g_off[NN + 1];
__device__ int g_pos[NN];
__device__ int g_csrc[EE];                 // (src<<3)|et in CSR order

// ---------------- fp32 K=64 SGEMM (in/out projections) ----------------
#define AS_STR 132
#define BS_STR 72
#define GEMM_SMEM ((64 * AS_STR + 64 * BS_STR) * 4)

__global__ __launch_bounds__(128)
void gemm64k(const float* __restrict__ A, int lda,
             const float* __restrict__ B,
             const float* __restrict__ bias, float* __restrict__ C, int ldc,
             int M, int batched, int act)
{
    extern __shared__ float smem[];
    float (*As)[AS_STR] = reinterpret_cast<float (*)[AS_STR]>(smem);
    float (*Bs)[BS_STR] = reinterpret_cast<float (*)[BS_STR]>(smem + 64 * AS_STR);

    const int tid = threadIdx.x;
    const int rowBase = blockIdx.x * 128;
    const int colBase = blockIdx.y * 64;
    const int aoff = batched ? colBase : 0;

    #pragma unroll
    for (int i = 0; i < 16; i++) {
        int f = tid + i * 128;
        int r = f >> 4;
        int kq = (f & 15) << 2;
        int gr = rowBase + r;
        float4 v = make_float4(0.f, 0.f, 0.f, 0.f);
        if (gr < M) v = *reinterpret_cast<const float4*>(A + (size_t)gr * lda + aoff + kq);
        As[kq + 0][r] = v.x; As[kq + 1][r] = v.y; As[kq + 2][r] = v.z; As[kq + 3][r] = v.w;
    }
    #pragma unroll
    for (int i = 0; i < 8; i++) {
        int f = tid + i * 128;
        int j = f >> 4;
        int kq = (f & 15) << 2;
        const float* brow = batched ? (B + (size_t)colBase * 64 + j * 64)
                                    : (B + (size_t)(colBase + j) * 64);
        float4 v = *reinterpret_cast<const float4*>(brow + kq);
        Bs[kq + 0][j] = v.x; Bs[kq + 1][j] = v.y; Bs[kq + 2][j] = v.z; Bs[kq + 3][j] = v.w;
    }
    __syncthreads();

    const int tx = tid & 7;
    const int ty = tid >> 3;

    unsigned long long acc[8][4];
    #pragma unroll
    for (int i = 0; i < 8; i++)
        #pragma unroll
        for (int j = 0; j < 4; j++) acc[i][j] = 0ULL;

    #pragma unroll
    for (int k = 0; k < 64; k++) {
        const float4* ap = reinterpret_cast<const float4*>(&As[k][ty * 8]);
        float4 a03 = ap[0], a47 = ap[1];
        float a[8] = {a03.x, a03.y, a03.z, a03.w, a47.x, a47.y, a47.z, a47.w};
        const ulonglong2* bp = reinterpret_cast<const ulonglong2*>(&Bs[k][tx * 8]);
        ulonglong2 bb0 = bp[0], bb1 = bp[1];
        unsigned long long b2[4] = {bb0.x, bb0.y, bb1.x, bb1.y};
        #pragma unroll
        for (int i = 0; i < 8; i++) {
            unsigned long long a2;
            asm("mov.b64 %0, {%1, %1};" : "=l"(a2) : "f"(a[i]));
            #pragma unroll
            for (int j = 0; j < 4; j++)
                asm("fma.rn.f32x2 %0, %1, %2, %0;" : "+l"(acc[i][j]) : "l"(a2), "l"(b2[j]));
        }
    }

    #pragma unroll
    for (int i = 0; i < 8; i++) {
        int gr = rowBase + ty * 8 + i;
        if (gr >= M) continue;
        #pragma unroll
        for (int j = 0; j < 4; j++) {
            float lo, hi;
            asm("mov.b64 {%0, %1}, %2;" : "=f"(lo), "=f"(hi) : "l"(acc[i][j]));
            int col = colBase + tx * 8 + 2 * j;
            if (bias) { lo += bias[col]; hi += bias[col + 1]; }
            if (act == 1) { lo = fmaxf(lo, 0.f); hi = fmaxf(hi, 0.f); }
            *reinterpret_cast<float2*>(C + (size_t)gr * ldc + col) = make_float2(lo, hi);
        }
    }
}

// ================= bf16 split-precision mma.sync GEMM =================
#define BF_STR 72
#define SA_HI 0
#define SA_LO (128 * BF_STR * 2)
#define SB_HI (SA_LO + 128 * BF_STR * 2)
#define SB_LO (SB_HI + 64 * BF_STR * 2)
#define GEMMBF_SMEM (SB_LO + 64 * BF_STR * 2)

__device__ __forceinline__ uint32_t smem_u32(const void* p) {
    uint32_t a;
    asm("{ .reg .u64 t; cvta.to.shared.u64 t, %1; cvt.u32.u64 %0, t; }" : "=r"(a) : "l"(p));
    return a;
}
__device__ __forceinline__ uint32_t pack_bf2(float x, float y) {
    __nv_bfloat162 t = __floats2bfloat162_rn(x, y);
    return *reinterpret_cast<uint32_t*>(&t);
}

#define LDSM_X4(r0, r1, r2, r3, addr) \
    asm volatile("ldmatrix.sync.aligned.m8n8.x4.shared.b16 {%0,%1,%2,%3}, [%4];" \
                 : "=r"(r0), "=r"(r1), "=r"(r2), "=r"(r3) : "r"(addr))
#define LDSM_X4T(r0, r1, r2, r3, addr) \
    asm volatile("ldmatrix.sync.aligned.m8n8.x4.trans.shared.b16 {%0,%1,%2,%3}, [%4];" \
                 : "=r"(r0), "=r"(r1), "=r"(r2), "=r"(r3) : "r"(addr))
#define MMA_BF(c, a, b0, b1) \
    asm volatile("mma.sync.aligned.m16n8k16.row.col.f32.bf16.bf16.f32 " \
                 "{%0,%1,%2,%3},{%4,%5,%6,%7},{%8,%9},{%0,%1,%2,%3};" \
                 : "+f"((c)[0]), "+f"((c)[1]), "+f"((c)[2]), "+f"((c)[3]) \
                 : "r"((a)[0]), "r"((a)[1]), "r"((a)[2]), "r"((a)[3]), "r"(b0), "r"(b1))

__global__ __launch_bounds__(128)
void gemmbf(const float* __restrict__ A, int lda,
            const float* __restrict__ B,
            const float* __restrict__ bias, float* __restrict__ C, int ldc,
            int M, int batched, int act, int dscale)
{
    extern __shared__ float smem[];
    char* smemc = reinterpret_cast<char*>(smem);
    __nv_bfloat16* Ahi = reinterpret_cast<__nv_bfloat16*>(smemc + SA_HI);
    __nv_bfloat16* Alo = reinterpret_cast<__nv_bfloat16*>(smemc + SA_LO);
    __nv_bfloat16* Bhi = reinterpret_cast<__nv_bfloat16*>(smemc + SB_HI);
    __nv_bfloat16* Blo = reinterpret_cast<__nv_bfloat16*>(smemc + SB_LO);

    const int tid = threadIdx.x, lane = tid & 31, warp = tid >> 5;
    const int rowBase = blockIdx.x * 128;
    const int colBase = blockIdx.y * 64;
    const int aoff = batched ? colBase : 0;

    #pragma unroll
    for (int i = 0; i < 16; i++) {
        int idx4 = tid + i * 128;
        int row = idx4 >> 4;
        int kq = (idx4 & 15) << 2;
        int gr = rowBase + row;
        float4 v = make_float4(0.f, 0.f, 0.f, 0.f);
        if (gr < M) v = *reinterpret_cast<const float4*>(A + (size_t)gr * lda + aoff + kq);
        float hx = __bfloat162float(__float2bfloat16_rn(v.x));
        float hy = __bfloat162float(__float2bfloat16_rn(v.y));
        float hz = __bfloat162float(__float2bfloat16_rn(v.z));
        float hw = __bfloat162float(__float2bfloat16_rn(v.w));
        uint32_t* ph = reinterpret_cast<uint32_t*>(&Ahi[row * BF_STR + kq]);
        uint32_t* pl = reinterpret_cast<uint32_t*>(&Alo[row * BF_STR + kq]);
        ph[0] = pack_bf2(hx, hy); ph[1] = pack_bf2(hz, hw);
        pl[0] = pack_bf2(v.x - hx, v.y - hy); pl[1] = pack_bf2(v.z - hz, v.w - hw);
    }
    #pragma unroll
    for (int i = 0; i < 8; i++) {
        int idx4 = tid + i * 128;
        int row = idx4 >> 4;
        int kq = (idx4 & 15) << 2;
        const float* brow = batched ? (B + (size_t)colBase * 64 + row * 64)
                                    : (B + (size_t)(colBase + row) * 64);
        float4 v = *reinterpret_cast<const float4*>(brow + kq);
        float hx = __bfloat162float(__float2bfloat16_rn(v.x));
        float hy = __bfloat162float(__float2bfloat16_rn(v.y));
        float hz = __bfloat162float(__float2bfloat16_rn(v.z));
        float hw = __bfloat162float(__float2bfloat16_rn(v.w));
        uint32_t* ph = reinterpret_cast<uint32_t*>(&Bhi[row * BF_STR + kq]);
        uint32_t* pl = reinterpret_cast<uint32_t*>(&Blo[row * BF_STR + kq]);
        ph[0] = pack_bf2(hx, hy); ph[1] = pack_bf2(hz, hw);
        pl[0] = pack_bf2(v.x - hx, v.y - hy); pl[1] = pack_bf2(v.z - hz, v.w - hw);
    }
    __syncthreads();

    uint32_t sbase = smem_u32(smemc);
    uint32_t aRow = warp * 32 + (lane & 15);
    uint32_t aCol = (lane >> 4) << 3;
    uint32_t aHiAddr = sbase + SA_HI + (aRow * BF_STR + aCol) * 2;
    uint32_t aLoAddr = sbase + SA_LO + (aRow * BF_STR + aCol) * 2;
    uint32_t bN = (lane & 7) + ((lane >> 4) << 3);
    uint32_t bK = ((lane >> 3) & 1) << 3;
    uint32_t bHiAddr = sbase + SB_HI + (bN * BF_STR + bK) * 2;
    uint32_t bLoAddr = sbase + SB_LO + (bN * BF_STR + bK) * 2;

    float c[2][8][4];
    #pragma unroll
    for (int a = 0; a < 2; a++)
        #pragma unroll
        for (int n = 0; n < 8; n++)
            #pragma unroll
            for (int j = 0; j < 4; j++) c[a][n][j] = 0.f;

    #pragma unroll
    for (int ks = 0; ks < 4; ks++) {
        uint32_t ka = ks * 32;
        uint32_t ah[2][4], al[2][4];
        LDSM_X4(ah[0][0], ah[0][1], ah[0][2], ah[0][3], aHiAddr + ka);
        LDSM_X4(ah[1][0], ah[1][1], ah[1][2], ah[1][3], aHiAddr + 16 * BF_STR * 2 + ka);
        LDSM_X4(al[0][0], al[0][1], al[0][2], al[0][3], aLoAddr + ka);
        LDSM_X4(al[1][0], al[1][1], al[1][2], al[1][3], aLoAddr + 16 * BF_STR * 2 + ka);
        #pragma unroll
        for (int p = 0; p < 4; p++) {
            uint32_t bo = p * 16 * BF_STR * 2 + ka;
            uint32_t bh0, bh1, bh2, bh3, bl0, bl1, bl2, bl3;
            LDSM_X4T(bh0, bh1, bh2, bh3, bHiAddr + bo);
            LDSM_X4T(bl0, bl1, bl2, bl3, bLoAddr + bo);
            #pragma unroll
            for (int a = 0; a < 2; a++) {
                MMA_BF(c[a][2 * p],     ah[a], bh0, bh1);
                MMA_BF(c[a][2 * p],     ah[a], bl0, bl1);
                MMA_BF(c[a][2 * p],     al[a], bh0, bh1);
                MMA_BF(c[a][2 * p + 1], ah[a], bh2, bh3);
                MMA_BF(c[a][2 * p + 1], ah[a], bl2, bl3);
                MMA_BF(c[a][2 * p + 1], al[a], bh2, bh3);
            }
        }
    }

    float ds = 1.f;
    if (dscale) ds = 1.f / g_denom[blockIdx.y];

    #pragma unroll
    for (int a = 0; a < 2; a++) {
        int gr0 = rowBase + warp * 32 + a * 16 + (lane >> 2);
        #pragma unroll
        for (int n = 0; n < 8; n++) {
            int col = colBase + n * 8 + (lane & 3) * 2;
            float lo0 = c[a][n][0] * ds, hi0 = c[a][n][1] * ds;
            float lo1 = c[a][n][2] * ds, hi1 = c[a][n][3] * ds;
            if (bias) {
                float bx = bias[col], by = bias[col + 1];
                lo0 += bx; hi0 += by; lo1 += bx; hi1 += by;
            }
            if (act == 1) {
                lo0 = fmaxf(lo0, 0.f); hi0 = fmaxf(hi0, 0.f);
                lo1 = fmaxf(lo1, 0.f); hi1 = fmaxf(hi1, 0.f);
            }
            if (gr0 < M)
                *reinterpret_cast<float2*>(C + (size_t)gr0 * ldc + col) = make_float2(lo0, hi0);
            if (gr0 + 8 < M)
                *reinterpret_cast<float2*>(C + (size_t)(gr0 + 8) * ldc + col) = make_float2(lo1, hi1);
        }
    }
}

// ---------------- CSR build ----------------
__global__ __launch_bounds__(256)
void zerodeg_k()
{
    int i = blockIdx.x * 256 + threadIdx.x;
    if (i < NN) g_deg[i] = 0;
}

__global__ __launch_bounds__(256)
void hist_k(const int* __restrict__ ei)
{
    int e = blockIdx.x * 256 + threadIdx.x;
    if (e < EE) atomicAdd(&g_deg[ei[EE + e]], 1);
}

__global__ __launch_bounds__(1024)
void scan_k()
{
    __shared__ int s[1024];
    __shared__ int carry_s;
    int tid = threadIdx.x;
    if (tid == 0) carry_s = 0;
    __syncthreads();
    for (int base = 0; base < NN; base += 4096) {
        int i0 = base + tid * 4;
        int v0 = (i0 + 0 < NN) ? g_deg[i0 + 0] : 0;
        int v1 = (i0 + 1 < NN) ? g_deg[i0 + 1] : 0;
        int v2 = (i0 + 2 < NN) ? g_deg[i0 + 2] : 0;
        int v3 = (i0 + 3 < NN) ? g_deg[i0 + 3] : 0;
        int tsum = v0 + v1 + v2 + v3;
        int val = tsum;
        s[tid] = val;
        __syncthreads();
        #pragma unroll
        for (int off = 1; off < 1024; off <<= 1) {
            int t = (tid >= off) ? s[tid - off] : 0;
            __syncthreads();
            val += t;
            s[tid] = val;
            __syncthreads();
        }
        int carry = carry_s;
        int o0 = carry + val - tsum;
        int o1 = o0 + v0, o2 = o1 + v1, o3 = o2 + v2;
        if (i0 + 0 < NN) { g_off[i0 + 0] = o0; g_pos[i0 + 0] = o0; }
        if (i0 + 1 < NN) { g_off[i0 + 1] = o1; g_pos[i0 + 1] = o1; }
        if (i0 + 2 < NN) { g_off[i0 + 2] = o2; g_pos[i0 + 2] = o2; }
        if (i0 + 3 < NN) { g_off[i0 + 3] = o3; g_pos[i0 + 3] = o3; }
        __syncthreads();
        if (tid == 1023) carry_s = carry + val;
        __syncthreads();
    }
    if (tid == 0) g_off[NN] = EE;
}

__global__ __launch_bounds__(256)
void fill_k(const int* __restrict__ ei, const int* __restrict__ et)
{
    int e = blockIdx.x * 256 + threadIdx.x;
    if (e >= EE) return;
    int dst = ei[EE + e];
    int p = atomicAdd(&g_pos[dst], 1);
    g_csrc[p] = (ei[e] << 3) | et[e];
}

// ---------------- attention projections (also zeroes denom for the layer) ----
__global__ __launch_bounds__(256)
void attproj_k(const float* __restrict__ h, const float* __restrict__ W_att)
{
    __shared__ float hs[16][65];
    __shared__ float ws[16][65];
    int tid = threadIdx.x;
    int nodeBase = blockIdx.x * 16;
    for (int i = tid; i < 16 * 64; i += 256) {
        int o = i >> 6, c = i & 63;
        ws[o][c] = W_att[(o & 7) * 128 + ((o >> 3) << 6) + c];
        int n = nodeBase + o;
        hs[o][c] = (n < NN) ? h[n * 64 + c] : 0.f;
    }
    __syncthreads();
    int nd = tid >> 4, o = tid & 15;
    float s = 0.f;
    #pragma unroll
    for (int c = 0; c < 64; c++) s += hs[nd][c] * ws[o][c];
    int n = nodeBase + nd;
    if (n < NN) g_ap[n * 16 + o] = s;
    if (blockIdx.x == 0 && tid < RR) g_denom[tid] = 0.f;
}

// ---------------- fused score+exp+aggregate + denom accumulation ----------------
// warp per node, half-warp per edge, float4 h gathers; unnormalized sums to g_spre.
__global__ __launch_bounds__(256)
void aggscatter_k(const float* __restrict__ h, const float* __restrict__ b_att)
{
    __shared__ float sbatt[RR];
    __shared__ float sdsum[RR];
    int tid = threadIdx.x;
    if (tid < RR) { sbatt[tid] = b_att[tid]; sdsum[tid] = 0.f; }
    __syncthreads();

    int warp = tid >> 5, lane = tid & 31;
    int half = lane >> 4;
    int c4 = (lane & 15) * 4;
    int n = blockIdx.x * 8 + warp;

    float4 acc[8];
    #pragma unroll
    for (int r = 0; r < 8; r++) acc[r] = make_float4(0.f, 0.f, 0.f, 0.f);
    float dent[8];
    #pragma unroll
    for (int r = 0; r < 8; r++) dent[r] = 0.f;

    if (n < NN) {
        int beg = g_off[n], end = g_off[n + 1];
        for (int b = beg; b < end; b += 8) {
            int pk[4]; float ex[4];
            #pragma unroll
            for (int i = 0; i < 4; i++) {
                int j = b + 2 * i + half;
                int jc = (j < end) ? j : beg;
                pk[i] = g_csrc[jc];
                int t = pk[i] & 7;
                int s = pk[i] >> 3;
                float sc = g_ap[s * 16 + t] + g_ap[n * 16 + 8 + t] + sbatt[t];
                sc = (sc > 0.f) ? sc : NEG_SLOPE * sc;
                ex[i] = (j < end) ? __expf(sc) : 0.f;
            }
            float4 v[4];
            #pragma unroll
            for (int i = 0; i < 4; i++)
                v[i] = *reinterpret_cast<const float4*>(&h[(pk[i] >> 3) * 64 + c4]);
            #pragma unroll
            for (int i = 0; i < 4; i++) {
                int er = pk[i] & 7;
                #pragma unroll
                for (int r = 0; r < 8; r++)
                    if (er == r) {
                        acc[r].x += ex[i] * v[i].x; acc[r].y += ex[i] * v[i].y;
                        acc[r].z += ex[i] * v[i].z; acc[r].w += ex[i] * v[i].w;
                        dent[r] += ex[i];
                    }
            }
        }

        // fold the two half-warp edge streams
        #pragma unroll
        for (int r = 0; r < 8; r++) {
            acc[r].x += __shfl_xor_sync(0xffffffffu, acc[r].x, 16);
            acc[r].y += __shfl_xor_sync(0xffffffffu, acc[r].y, 16);
            acc[r].z += __shfl_xor_sync(0xffffffffu, acc[r].z, 16);
            acc[r].w += __shfl_xor_sync(0xffffffffu, acc[r].w, 16);
        }

        if (half == 0) {
            size_t base = (size_t)n * 512;
            #pragma unroll
            for (int r = 0; r < 8; r++)
                *reinterpret_cast<float4*>(&g_spre[base + r * 64 + c4]) = acc[r];
        }
    }

    // denom: lanes 0 and 16 hold each half's per-type ex sums (dent identical
    // across the 16 lanes of a half). Fold to lane 0, stage in smem, one
    // global atomic set per block.
    if ((lane & 15) == 0) {
        #pragma unroll
        for (int r = 0; r < 8; r++) {
            float d = dent[r] + __shfl_xor_sync(0x00010001u << (lane & 31 ? 0 : 0), dent[r], 16);
            // NOTE: shfl above must be full-mask; replaced below
        }
    }
    // correct, simple fold: all lanes participate
    #pragma unroll
    for (int r = 0; r < 8; r++) {
        float d = dent[r] + __shfl_xor_sync(0xffffffffu, dent[r], 16);
        if (lane == 0 && d != 0.f) atomicAdd(&sdsum[r], d);
    }
    __syncthreads();
    if (tid < RR) {
        float d = sdsum[tid];
        if (d != 0.f) atomicAdd(&g_denom[tid], d);
    }
}

// ---------------- gate*prod mean + residual + LN + relu (R12-proven) ----
__global__ __launch_bounds__(256)
void combine_k(const float* __restrict__ hin, float* __restrict__ hout,
               const float* __restrict__ b_gate,
               const float* __restrict__ gamma, const float* __restrict__ beta)
{
    int tid = threadIdx.x;
    int warp = tid >> 5, lane = tid & 31;
    int half = lane >> 4;
    int c4 = (lane & 15) * 4;
    int n = blockIdx.x * 8 + warp;
    if (n >= NN) return;

    size_t base = (size_t)n * 512;
    float4 hx = make_float4(0.f, 0.f, 0.f, 0.f);
    #pragma unroll
    for (int rr = 0; rr < 4; rr++) {
        int r = 2 * rr + half;
        int o = r * 64 + c4;
        float4 gp = *reinterpret_cast<const float4*>(&g_gate[base + o]);
        float4 pv = *reinterpret_cast<const float4*>(&g_prod[base + o]);
        float4 bg = *reinterpret_cast<const float4*>(&b_gate[o]);
        hx.x += pv.x / (1.f + __expf(-(gp.x + bg.x)));
        hx.y += pv.y / (1.f + __expf(-(gp.y + bg.y)));
        hx.z += pv.z / (1.f + __expf(-(gp.z + bg.z)));
        hx.w += pv.w / (1.f + __expf(-(gp.w + bg.w)));
    }
    hx.x += __shfl_xor_sync(0xffffffffu, hx.x, 16);
    hx.y += __shfl_xor_sync(0xffffffffu, hx.y, 16);
    hx.z += __shfl_xor_sync(0xffffffffu, hx.z, 16);
    hx.w += __shfl_xor_sync(0xffffffffu, hx.w, 16);

    float4 hv = *reinterpret_cast<const float4*>(&hin[(size_t)n * 64 + c4]);
    float h0 = hv.x + hx.x * 0.125f;
    float h1 = hv.y + hx.y * 0.125f;
    float h2 = hv.z + hx.z * 0.125f;
    float h3 = hv.w + hx.w * 0.125f;

    float s = h0 + h1 + h2 + h3;
    #pragma unroll
    for (int o = 8; o > 0; o >>= 1) s += __shfl_xor_sync(0xffffffffu, s, o);
    float mu = s * (1.f / 64.f);
    float d0 = h0 - mu, d1 = h1 - mu, d2 = h2 - mu, d3 = h3 - mu;
    float v = d0 * d0 + d1 * d1 + d2 * d2 + d3 * d3;
    #pragma unroll
    for (int o = 8; o > 0; o >>= 1) v += __shfl_xor_sync(0xffffffffu, v, o);
    float rs = rsqrtf(v * (1.f / 64.f) + LN_EPS);

    if (half == 0) {
        float4 gm = *reinterpret_cast<const float4*>(&gamma[c4]);
        float4 bt = *reinterpret_cast<const float4*>(&beta[c4]);
        float4 o4;
        o4.x = fmaxf(d0 * rs * gm.x + bt.x, 0.f);
        o4.y = fmaxf(d1 * rs * gm.y + bt.y, 0.f);
        o4.z = fmaxf(d2 * rs * gm.z + bt.z, 0.f);
        o4.w = fmaxf(d3 * rs * gm.w + bt.w, 0.f);
        *reinterpret_cast<float4*>(&hout[(size_t)n * 64 + c4]) = o4;
    }
}

// ---------------- launch ----------------
extern "C" void kernel_launch(void* const* d_in, const int* in_sizes, int n_in,
                              void* d_out, int out_size)
{
    const float* x      = (const float*)d_in[0];
    const int*   ei     = (const int*)  d_in[1];
    const int*   et     = (const int*)  d_in[2];
    const float* W_in   = (const float*)d_in[3];
    const float* b_in   = (const float*)d_in[4];
    const float* W_rel  = (const float*)d_in[5];
    const float* W_gate = (const float*)d_in[6];
    const float* b_gate = (const float*)d_in[7];
    const float* W_att  = (const float*)d_in[8];
    const float* b_att  = (const float*)d_in[9];
    const float* ln_g   = (const float*)d_in[10];
    const float* ln_b   = (const float*)d_in[11];
    const float* W_out  = (const float*)d_in[12];
    const float* b_out  = (const float*)d_in[13];
    float* out = (float*)d_out;

    float *hbuf, *sprep, *gatep, *prodp;
    cudaGetSymbolAddress((void**)&hbuf,  g_h);
    cudaGetSymbolAddress((void**)&sprep, g_spre);
    cudaGetSymbolAddress((void**)&gatep, g_gate);
    cudaGetSymbolAddress((void**)&prodp, g_prod);
    float* h0p = hbuf;
    float* h1p = hbuf + (size_t)NN * HH;

    cudaFuncSetAttribute(gemm64k, cudaFuncAttributeMaxDynamicSharedMemorySize, GEMM_SMEM);
    cudaFuncSetAttribute(gemmbf,  cudaFuncAttributeMaxDynamicSharedMemorySize, GEMMBF_SMEM);

    static cudaStream_t s2 = nullptr;
    static cudaEvent_t evF = nullptr, evG = nullptr, evC = nullptr;
    if (!s2) {
        cudaStreamCreateWithFlags(&s2, cudaStreamNonBlocking);
        cudaEventCreateWithFlags(&evF, cudaEventDisableTiming);
        cudaEventCreateWithFlags(&evG, cudaEventDisableTiming);
        cudaEventCreateWithFlags(&evC, cudaEventDisableTiming);
    }

    // fork: CSR build on s2, input projection on main
    cudaEventRecord(evF, 0);
    cudaStreamWaitEvent(s2, evF, 0);
    zerodeg_k<<<(NN + 255) / 256, 256, 0, s2>>>();
    hist_k<<<(EE + 255) / 256, 256, 0, s2>>>(ei);
    scan_k<<<1, 1024, 0, s2>>>();
    fill_k<<<(EE + 255) / 256, 256, 0, s2>>>(ei, et);
    cudaEventRecord(evC, s2);

    gemm64k<<<dim3((NN + 127) / 128, 1), 128, GEMM_SMEM>>>(x, 64, W_in, b_in, h0p, 64, NN, 0, 1);

    float* hc = h0p;
    float* hn = h1p;
    for (int layer = 0; layer < LL; layer++) {
        // fork: gate GEMM (bf16 split) on s2
        cudaEventRecord(evF, 0);
        cudaStreamWaitEvent(s2, evF, 0);
        gemmbf<<<dim3((NN + 127) / 128, 8), 128, GEMMBF_SMEM, s2>>>(hc, 64, W_gate, nullptr, gatep, 512, NN, 0, 0, 0);
        cudaEventRecord(evG, s2);

        // main: edge chain (score+exp+agg fused; denom applied in relgemm)
        attproj_k<<<(NN + 15) / 16, 256>>>(hc, W_att);
        if (layer == 0) cudaStreamWaitEvent(0, evC, 0);
        aggscatter_k<<<(NN + 7) / 8, 256>>>(hc, b_att);
        gemmbf<<<dim3((NN + 127) / 128, 8), 128, GEMMBF_SMEM>>>(sprep, 512, W_rel, nullptr, prodp, 512, NN, 1, 0, 1);

        cudaStreamWaitEvent(0, evG, 0);
        combine_k<<<(NN + 7) / 8, 256>>>(hc, hn, b_gate, ln_g + layer * 64, ln_b + layer * 64);
        float* tmp = hc; hc = hn; hn = tmp;
    }

    gemm64k<<<dim3((NN + 127) / 128, 1), 128, GEMM_SMEM>>>(hc, 64, W_out, b_out, out, 64, NN, 0, 0);
}

// round 15
// speedup vs baseline: 1.1721x; 1.1721x over previous
#include <cuda_runtime.h>
#include <cuda_bf16.h>
#include <cuda_fp16.h>
#include <cstdint>

// ---------------- problem constants ----------------
#define NN 50000
#define EE 800000
#define HH 64
#define RR 8
#define LL 3
#define LN_EPS 1e-5f
#define NEG_SLOPE 0.2f

// ---------------- device scratch ----------------
__device__ float g_h[2 * NN * HH];          // ping-pong node features
__device__ __half g_prod[(size_t)NN * 512]; // relgemm output (fp16)
__device__ __half g_gate[(size_t)NN * 512]; // gate pre-activation (fp16)
__device__ float g_spre[(size_t)NN * 512];  // att-weighted h sums per (n,r)
__device__ float g_ap[NN * 16];             // attention projections
__device__ float g_exc[EE];                 // exp(score) in CSR order
__device__ float g_denom[RR];
__device__ int g_deg[NN];
__device__ int g_off[NN + 1];
__device__ int g_pos[NN];
__device__ int g_csrc[EE];                  // (src<<3)|et in CSR order
__device__ int g_cdst[EE];                  // dst in CSR order

// ---------------- fp32 K=64 SGEMM (in/out projections) ----------------
#define AS_STR 132
#define BS_STR 72
#define GEMM_SMEM ((64 * AS_STR + 64 * BS_STR) * 4)

__global__ __launch_bounds__(128)
void gemm64k(const float* __restrict__ A, int lda,
             const float* __restrict__ B,
             const float* __restrict__ bias, float* __restrict__ C, int ldc,
             int M, int batched, int act)
{
    extern __shared__ float smem[];
    float (*As)[AS_STR] = reinterpret_cast<float (*)[AS_STR]>(smem);
    float (*Bs)[BS_STR] = reinterpret_cast<float (*)[BS_STR]>(smem + 64 * AS_STR);

    const int tid = threadIdx.x;
    const int rowBase = blockIdx.x * 128;
    const int colBase = blockIdx.y * 64;
    const int aoff = batched ? colBase : 0;

    #pragma unroll
    for (int i = 0; i < 16; i++) {
        int f = tid + i * 128;
        int r = f >> 4;
        int kq = (f & 15) << 2;
        int gr = rowBase + r;
        float4 v = make_float4(0.f, 0.f, 0.f, 0.f);
        if (gr < M) v = *reinterpret_cast<const float4*>(A + (size_t)gr * lda + aoff + kq);
        As[kq + 0][r] = v.x; As[kq + 1][r] = v.y; As[kq + 2][r] = v.z; As[kq + 3][r] = v.w;
    }
    #pragma unroll
    for (int i = 0; i < 8; i++) {
        int f = tid + i * 128;
        int j = f >> 4;
        int kq = (f & 15) << 2;
        const float* brow = batched ? (B + (size_t)colBase * 64 + j * 64)
                                    : (B + (size_t)(colBase + j) * 64);
        float4 v = *reinterpret_cast<const float4*>(brow + kq);
        Bs[kq + 0][j] = v.x; Bs[kq + 1][j] = v.y; Bs[kq + 2][j] = v.z; Bs[kq + 3][j] = v.w;
    }
    __syncthreads();

    const int tx = tid & 7;
    const int ty = tid >> 3;

    unsigned long long acc[8][4];
    #pragma unroll
    for (int i = 0; i < 8; i++)
        #pragma unroll
        for (int j = 0; j < 4; j++) acc[i][j] = 0ULL;

    #pragma unroll
    for (int k = 0; k < 64; k++) {
        const float4* ap = reinterpret_cast<const float4*>(&As[k][ty * 8]);
        float4 a03 = ap[0], a47 = ap[1];
        float a[8] = {a03.x, a03.y, a03.z, a03.w, a47.x, a47.y, a47.z, a47.w};
        const ulonglong2* bp = reinterpret_cast<const ulonglong2*>(&Bs[k][tx * 8]);
        ulonglong2 bb0 = bp[0], bb1 = bp[1];
        unsigned long long b2[4] = {bb0.x, bb0.y, bb1.x, bb1.y};
        #pragma unroll
        for (int i = 0; i < 8; i++) {
            unsigned long long a2;
            asm("mov.b64 %0, {%1, %1};" : "=l"(a2) : "f"(a[i]));
            #pragma unroll
            for (int j = 0; j < 4; j++)
                asm("fma.rn.f32x2 %0, %1, %2, %0;" : "+l"(acc[i][j]) : "l"(a2), "l"(b2[j]));
        }
    }

    #pragma unroll
    for (int i = 0; i < 8; i++) {
        int gr = rowBase + ty * 8 + i;
        if (gr >= M) continue;
        #pragma unroll
        for (int j = 0; j < 4; j++) {
            float lo, hi;
            asm("mov.b64 {%0, %1}, %2;" : "=f"(lo), "=f"(hi) : "l"(acc[i][j]));
            int col = colBase + tx * 8 + 2 * j;
            if (bias) { lo += bias[col]; hi += bias[col + 1]; }
            if (act == 1) { lo = fmaxf(lo, 0.f); hi = fmaxf(hi, 0.f); }
            *reinterpret_cast<float2*>(C + (size_t)gr * ldc + col) = make_float2(lo, hi);
        }
    }
}

// ================= bf16 split-precision mma.sync GEMM =================
// half_out: write __half2 into a __half* C (ldc in elements).
#define BF_STR 72
#define SA_HI 0
#define SA_LO (128 * BF_STR * 2)
#define SB_HI (SA_LO + 128 * BF_STR * 2)
#define SB_LO (SB_HI + 64 * BF_STR * 2)
#define GEMMBF_SMEM (SB_LO + 64 * BF_STR * 2)

__device__ __forceinline__ uint32_t smem_u32(const void* p) {
    uint32_t a;
    asm("{ .reg .u64 t; cvta.to.shared.u64 t, %1; cvt.u32.u64 %0, t; }" : "=r"(a) : "l"(p));
    return a;
}
__device__ __forceinline__ uint32_t pack_bf2(float x, float y) {
    __nv_bfloat162 t = __floats2bfloat162_rn(x, y);
    return *reinterpret_cast<uint32_t*>(&t);
}

#define LDSM_X4(r0, r1, r2, r3, addr) \
    asm volatile("ldmatrix.sync.aligned.m8n8.x4.shared.b16 {%0,%1,%2,%3}, [%4];" \
                 : "=r"(r0), "=r"(r1), "=r"(r2), "=r"(r3) : "r"(addr))
#define LDSM_X4T(r0, r1, r2, r3, addr) \
    asm volatile("ldmatrix.sync.aligned.m8n8.x4.trans.shared.b16 {%0,%1,%2,%3}, [%4];" \
                 : "=r"(r0), "=r"(r1), "=r"(r2), "=r"(r3) : "r"(addr))
#define MMA_BF(c, a, b0, b1) \
    asm volatile("mma.sync.aligned.m16n8k16.row.col.f32.bf16.bf16.f32 " \
                 "{%0,%1,%2,%3},{%4,%5,%6,%7},{%8,%9},{%0,%1,%2,%3};" \
                 : "+f"((c)[0]), "+f"((c)[1]), "+f"((c)[2]), "+f"((c)[3]) \
                 : "r"((a)[0]), "r"((a)[1]), "r"((a)[2]), "r"((a)[3]), "r"(b0), "r"(b1))

__global__ __launch_bounds__(128)
void gemmbf(const float* __restrict__ A, int lda,
            const float* __restrict__ B,
            const float* __restrict__ bias, void* __restrict__ Cv, int ldc,
            int M, int batched, int act, int half_out)
{
    extern __shared__ float smem[];
    char* smemc = reinterpret_cast<char*>(smem);
    __nv_bfloat16* Ahi = reinterpret_cast<__nv_bfloat16*>(smemc + SA_HI);
    __nv_bfloat16* Alo = reinterpret_cast<__nv_bfloat16*>(smemc + SA_LO);
    __nv_bfloat16* Bhi = reinterpret_cast<__nv_bfloat16*>(smemc + SB_HI);
    __nv_bfloat16* Blo = reinterpret_cast<__nv_bfloat16*>(smemc + SB_LO);

    const int tid = threadIdx.x, lane = tid & 31, warp = tid >> 5;
    const int rowBase = blockIdx.x * 128;
    const int colBase = blockIdx.y * 64;
    const int aoff = batched ? colBase : 0;

    #pragma unroll
    for (int i = 0; i < 16; i++) {
        int idx4 = tid + i * 128;
        int row = idx4 >> 4;
        int kq = (idx4 & 15) << 2;
        int gr = rowBase + row;
        float4 v = make_float4(0.f, 0.f, 0.f, 0.f);
        if (gr < M) v = *reinterpret_cast<const float4*>(A + (size_t)gr * lda + aoff + kq);
        float hx = __bfloat162float(__float2bfloat16_rn(v.x));
        float hy = __bfloat162float(__float2bfloat16_rn(v.y));
        float hz = __bfloat162float(__float2bfloat16_rn(v.z));
        float hw = __bfloat162float(__float2bfloat16_rn(v.w));
        uint32_t* ph = reinterpret_cast<uint32_t*>(&Ahi[row * BF_STR + kq]);
        uint32_t* pl = reinterpret_cast<uint32_t*>(&Alo[row * BF_STR + kq]);
        ph[0] = pack_bf2(hx, hy); ph[1] = pack_bf2(hz, hw);
        pl[0] = pack_bf2(v.x - hx, v.y - hy); pl[1] = pack_bf2(v.z - hz, v.w - hw);
    }
    #pragma unroll
    for (int i = 0; i < 8; i++) {
        int idx4 = tid + i * 128;
        int row = idx4 >> 4;
        int kq = (idx4 & 15) << 2;
        const float* brow = batched ? (B + (size_t)colBase * 64 + row * 64)
                                    : (B + (size_t)(colBase + row) * 64);
        float4 v = *reinterpret_cast<const float4*>(brow + kq);
        float hx = __bfloat162float(__float2bfloat16_rn(v.x));
        float hy = __bfloat162float(__float2bfloat16_rn(v.y));
        float hz = __bfloat162float(__float2bfloat16_rn(v.z));
        float hw = __bfloat162float(__float2bfloat16_rn(v.w));
        uint32_t* ph = reinterpret_cast<uint32_t*>(&Bhi[row * BF_STR + kq]);
        uint32_t* pl = reinterpret_cast<uint32_t*>(&Blo[row * BF_STR + kq]);
        ph[0] = pack_bf2(hx, hy); ph[1] = pack_bf2(hz, hw);
        pl[0] = pack_bf2(v.x - hx, v.y - hy); pl[1] = pack_bf2(v.z - hz, v.w - hw);
    }
    __syncthreads();

    uint32_t sbase = smem_u32(smemc);
    uint32_t aRow = warp * 32 + (lane & 15);
    uint32_t aCol = (lane >> 4) << 3;
    uint32_t aHiAddr = sbase + SA_HI + (aRow * BF_STR + aCol) * 2;
    uint32_t aLoAddr = sbase + SA_LO + (aRow * BF_STR + aCol) * 2;
    uint32_t bN = (lane & 7) + ((lane >> 4) << 3);
    uint32_t bK = ((lane >> 3) & 1) << 3;
    uint32_t bHiAddr = sbase + SB_HI + (bN * BF_STR + bK) * 2;
    uint32_t bLoAddr = sbase + SB_LO + (bN * BF_STR + bK) * 2;

    float c[2][8][4];
    #pragma unroll
    for (int a = 0; a < 2; a++)
        #pragma unroll
        for (int n = 0; n < 8; n++)
            #pragma unroll
            for (int j = 0; j < 4; j++) c[a][n][j] = 0.f;

    #pragma unroll
    for (int ks = 0; ks < 4; ks++) {
        uint32_t ka = ks * 32;
        uint32_t ah[2][4], al[2][4];
        LDSM_X4(ah[0][0], ah[0][1], ah[0][2], ah[0][3], aHiAddr + ka);
        LDSM_X4(ah[1][0], ah[1][1], ah[1][2], ah[1][3], aHiAddr + 16 * BF_STR * 2 + ka);
        LDSM_X4(al[0][0], al[0][1], al[0][2], al[0][3], aLoAddr + ka);
        LDSM_X4(al[1][0], al[1][1], al[1][2], al[1][3], aLoAddr + 16 * BF_STR * 2 + ka);
        #pragma unroll
        for (int p = 0; p < 4; p++) {
            uint32_t bo = p * 16 * BF_STR * 2 + ka;
            uint32_t bh0, bh1, bh2, bh3, bl0, bl1, bl2, bl3;
            LDSM_X4T(bh0, bh1, bh2, bh3, bHiAddr + bo);
            LDSM_X4T(bl0, bl1, bl2, bl3, bLoAddr + bo);
            #pragma unroll
            for (int a = 0; a < 2; a++) {
                MMA_BF(c[a][2 * p],     ah[a], bh0, bh1);
                MMA_BF(c[a][2 * p],     ah[a], bl0, bl1);
                MMA_BF(c[a][2 * p],     al[a], bh0, bh1);
                MMA_BF(c[a][2 * p + 1], ah[a], bh2, bh3);
                MMA_BF(c[a][2 * p + 1], ah[a], bl2, bl3);
                MMA_BF(c[a][2 * p + 1], al[a], bh2, bh3);
            }
        }
    }

    #pragma unroll
    for (int a = 0; a < 2; a++) {
        int gr0 = rowBase + warp * 32 + a * 16 + (lane >> 2);
        #pragma unroll
        for (int n = 0; n < 8; n++) {
            int col = colBase + n * 8 + (lane & 3) * 2;
            float lo0 = c[a][n][0], hi0 = c[a][n][1];
            float lo1 = c[a][n][2], hi1 = c[a][n][3];
            if (bias) {
                float bx = bias[col], by = bias[col + 1];
                lo0 += bx; hi0 += by; lo1 += bx; hi1 += by;
            }
            if (act == 1) {
                lo0 = fmaxf(lo0, 0.f); hi0 = fmaxf(hi0, 0.f);
                lo1 = fmaxf(lo1, 0.f); hi1 = fmaxf(hi1, 0.f);
            }
            if (half_out) {
                __half* Ch = reinterpret_cast<__half*>(Cv);
                if (gr0 < M)
                    *reinterpret_cast<__half2*>(Ch + (size_t)gr0 * ldc + col) = __floats2half2_rn(lo0, hi0);
                if (gr0 + 8 < M)
                    *reinterpret_cast<__half2*>(Ch + (size_t)(gr0 + 8) * ldc + col) = __floats2half2_rn(lo1, hi1);
            } else {
                float* Cf = reinterpret_cast<float*>(Cv);
                if (gr0 < M)
                    *reinterpret_cast<float2*>(Cf + (size_t)gr0 * ldc + col) = make_float2(lo0, hi0);
                if (gr0 + 8 < M)
                    *reinterpret_cast<float2*>(Cf + (size_t)(gr0 + 8) * ldc + col) = make_float2(lo1, hi1);
            }
        }
    }
}

// ---------------- CSR build ----------------
__global__ __launch_bounds__(256)
void zerodeg_k()
{
    int i = blockIdx.x * 256 + threadIdx.x;
    if (i < NN) g_deg[i] = 0;
}

__global__ __launch_bounds__(256)
void hist_k(const int* __restrict__ ei)
{
    int e = blockIdx.x * 256 + threadIdx.x;
    if (e < EE) atomicAdd(&g_deg[ei[EE + e]], 1);
}

__global__ __launch_bounds__(1024)
void scan_k()
{
    __shared__ int s[1024];
    __shared__ int carry_s;
    int tid = threadIdx.x;
    if (tid == 0) carry_s = 0;
    __syncthreads();
    for (int base = 0; base < NN; base += 4096) {
        int i0 = base + tid * 4;
        int v0 = (i0 + 0 < NN) ? g_deg[i0 + 0] : 0;
        int v1 = (i0 + 1 < NN) ? g_deg[i0 + 1] : 0;
        int v2 = (i0 + 2 < NN) ? g_deg[i0 + 2] : 0;
        int v3 = (i0 + 3 < NN) ? g_deg[i0 + 3] : 0;
        int tsum = v0 + v1 + v2 + v3;
        int val = tsum;
        s[tid] = val;
        __syncthreads();
        #pragma unroll
        for (int off = 1; off < 1024; off <<= 1) {
            int t = (tid >= off) ? s[tid - off] : 0;
            __syncthreads();
            val += t;
            s[tid] = val;
            __syncthreads();
        }
        int carry = carry_s;
        int o0 = carry + val - tsum;
        int o1 = o0 + v0, o2 = o1 + v1, o3 = o2 + v2;
        if (i0 + 0 < NN) { g_off[i0 + 0] = o0; g_pos[i0 + 0] = o0; }
        if (i0 + 1 < NN) { g_off[i0 + 1] = o1; g_pos[i0 + 1] = o1; }
        if (i0 + 2 < NN) { g_off[i0 + 2] = o2; g_pos[i0 + 2] = o2; }
        if (i0 + 3 < NN) { g_off[i0 + 3] = o3; g_pos[i0 + 3] = o3; }
        __syncthreads();
        if (tid == 1023) carry_s = carry + val;
        __syncthreads();
    }
    if (tid == 0) g_off[NN] = EE;
}

__global__ __launch_bounds__(256)
void fill_k(const int* __restrict__ ei, const int* __restrict__ et)
{
    int e = blockIdx.x * 256 + threadIdx.x;
    if (e >= EE) return;
    int dst = ei[EE + e];
    int p = atomicAdd(&g_pos[dst], 1);
    g_csrc[p] = (ei[e] << 3) | et[e];
    g_cdst[p] = dst;
}

// ---------------- attention projections ----------------
__global__ __launch_bounds__(256)
void attproj_k(const float* __restrict__ h, const float* __restrict__ W_att)
{
    __shared__ float hs[16][65];
    __shared__ float ws[16][65];
    int tid = threadIdx.x;
    int nodeBase = blockIdx.x * 16;
    for (int i = tid; i < 16 * 64; i += 256) {
        int o = i >> 6, c = i & 63;
        ws[o][c] = W_att[(o & 7) * 128 + ((o >> 3) << 6) + c];
        int n = nodeBase + o;
        hs[o][c] = (n < NN) ? h[n * 64 + c] : 0.f;
    }
    __syncthreads();
    int nd = tid >> 4, o = tid & 15;
    float s = 0.f;
    #pragma unroll
    for (int c = 0; c < 64; c++) s += hs[nd][c] * ws[o][c];
    int n = nodeBase + nd;
    if (n < NN) g_ap[n * 16 + o] = s;
    if (blockIdx.x == 0 && tid < RR) g_denom[tid] = 0.f;
}

// ---------------- scores + exp + denom, CSR order ----------
__global__ __launch_bounds__(256)
void scoreexp_k(const float* __restrict__ b_att)
{
    __shared__ float ssum[RR];
    int tid = threadIdx.x;
    if (tid < RR) ssum[tid] = 0.f;
    __syncthreads();
    int j = blockIdx.x * 256 + tid;
    if (j < EE) {
        int pk = g_csrc[j];
        int t = pk & 7;
        int s = pk >> 3;
        int d = g_cdst[j];
        float sc = g_ap[s * 16 + t] + g_ap[d * 16 + 8 + t] + b_att[t];
        sc = (sc > 0.f) ? sc : NEG_SLOPE * sc;
        float ex = __expf(sc);
        g_exc[j] = ex;
        atomicAdd(&ssum[t], ex);
    }
    __syncthreads();
    if (tid < RR) atomicAdd(&g_denom[tid], ssum[tid]);
}

// ---------------- aggregate att-weighted h[src] per (dst, r) ----------------
__global__ __launch_bounds__(256)
void aggscatter_k(const float* __restrict__ h)
{
    __shared__ float sden[RR];
    int tid = threadIdx.x;
    if (tid < RR) sden[tid] = 1.f / g_denom[tid];
    __syncthreads();

    int warp = tid >> 5, lane = tid & 31;
    int half = lane >> 4;
    int c4 = (lane & 15) * 4;
    int n = blockIdx.x * 8 + warp;
    if (n >= NN) return;

    float4 acc[8];
    #pragma unroll
    for (int r = 0; r < 8; r++) acc[r] = make_float4(0.f, 0.f, 0.f, 0.f);

    int beg = g_off[n], end = g_off[n + 1];
    for (int b = beg; b < end; b += 8) {
        int pk[4]; float at[4];
        #pragma unroll
        for (int i = 0; i < 4; i++) {
            int j = b + 2 * i + half;
            int jc = (j < end) ? j : beg;
            pk[i] = g_csrc[jc];
            float ex = g_exc[jc];
            at[i] = (j < end) ? ex * sden[pk[i] & 7] : 0.f;
        }
        float4 v[4];
        #pragma unroll
        for (int i = 0; i < 4; i++)
            v[i] = *reinterpret_cast<const float4*>(&h[(pk[i] >> 3) * 64 + c4]);
        #pragma unroll
        for (int i = 0; i < 4; i++) {
            int er = pk[i] & 7;
            #pragma unroll
            for (int r = 0; r < 8; r++)
                if (er == r) {
                    acc[r].x += at[i] * v[i].x; acc[r].y += at[i] * v[i].y;
                    acc[r].z += at[i] * v[i].z; acc[r].w += at[i] * v[i].w;
                }
        }
    }

    #pragma unroll
    for (int r = 0; r < 8; r++) {
        acc[r].x += __shfl_xor_sync(0xffffffffu, acc[r].x, 16);
        acc[r].y += __shfl_xor_sync(0xffffffffu, acc[r].y, 16);
        acc[r].z += __shfl_xor_sync(0xffffffffu, acc[r].z, 16);
        acc[r].w += __shfl_xor_sync(0xffffffffu, acc[r].w, 16);
    }

    if (half == 0) {
        size_t base = (size_t)n * 512;
        #pragma unroll
        for (int r = 0; r < 8; r++)
            *reinterpret_cast<float4*>(&g_spre[base + r * 64 + c4]) = acc[r];
    }
}

// ---------------- gate*prod mean + residual + LN + relu (fp16 gate/prod) ----
__global__ __launch_bounds__(256)
void combine_k(const float* __restrict__ hin, float* __restrict__ hout,
               const float* __restrict__ b_gate,
               const float* __restrict__ gamma, const float* __restrict__ beta)
{
    int tid = threadIdx.x;
    int warp = tid >> 5, lane = tid & 31;
    int half = lane >> 4;
    int c4 = (lane & 15) * 4;
    int n = blockIdx.x * 8 + warp;
    if (n >= NN) return;

    size_t base = (size_t)n * 512;
    float4 hx = make_float4(0.f, 0.f, 0.f, 0.f);
    #pragma unroll
    for (int rr = 0; rr < 4; rr++) {
        int r = 2 * rr + half;
        int o = r * 64 + c4;
        uint2 gu = *reinterpret_cast<const uint2*>(&g_gate[base + o]);
        uint2 pu = *reinterpret_cast<const uint2*>(&g_prod[base + o]);
        float2 g01 = __half22float2(*reinterpret_cast<__half2*>(&gu.x));
        float2 g23 = __half22float2(*reinterpret_cast<__half2*>(&gu.y));
        float2 p01 = __half22float2(*reinterpret_cast<__half2*>(&pu.x));
        float2 p23 = __half22float2(*reinterpret_cast<__half2*>(&pu.y));
        float4 bg = *reinterpret_cast<const float4*>(&b_gate[o]);
        hx.x += p01.x / (1.f + __expf(-(g01.x + bg.x)));
        hx.y += p01.y / (1.f + __expf(-(g01.y + bg.y)));
        hx.z += p23.x / (1.f + __expf(-(g23.x + bg.z)));
        hx.w += p23.y / (1.f + __expf(-(g23.y + bg.w)));
    }
    hx.x += __shfl_xor_sync(0xffffffffu, hx.x, 16);
    hx.y += __shfl_xor_sync(0xffffffffu, hx.y, 16);
    hx.z += __shfl_xor_sync(0xffffffffu, hx.z, 16);
    hx.w += __shfl_xor_sync(0xffffffffu, hx.w, 16);

    float4 hv = *reinterpret_cast<const float4*>(&hin[(size_t)n * 64 + c4]);
    float h0 = hv.x + hx.x * 0.125f;
    float h1 = hv.y + hx.y * 0.125f;
    float h2 = hv.z + hx.z * 0.125f;
    float h3 = hv.w + hx.w * 0.125f;

    float s = h0 + h1 + h2 + h3;
    #pragma unroll
    for (int o = 8; o > 0; o >>= 1) s += __shfl_xor_sync(0xffffffffu, s, o);
    float mu = s * (1.f / 64.f);
    float d0 = h0 - mu, d1 = h1 - mu, d2 = h2 - mu, d3 = h3 - mu;
    float v = d0 * d0 + d1 * d1 + d2 * d2 + d3 * d3;
    #pragma unroll
    for (int o = 8; o > 0; o >>= 1) v += __shfl_xor_sync(0xffffffffu, v, o);
    float rs = rsqrtf(v * (1.f / 64.f) + LN_EPS);

    if (half == 0) {
        float4 gm = *reinterpret_cast<const float4*>(&gamma[c4]);
        float4 bt = *reinterpret_cast<const float4*>(&beta[c4]);
        float4 o4;
        o4.x = fmaxf(d0 * rs * gm.x + bt.x, 0.f);
        o4.y = fmaxf(d1 * rs * gm.y + bt.y, 0.f);
        o4.z = fmaxf(d2 * rs * gm.z + bt.z, 0.f);
        o4.w = fmaxf(d3 * rs * gm.w + bt.w, 0.f);
        *reinterpret_cast<float4*>(&hout[(size_t)n * 64 + c4]) = o4;
    }
}

// ---------------- launch ----------------
extern "C" void kernel_launch(void* const* d_in, const int* in_sizes, int n_in,
                              void* d_out, int out_size)
{
    const float* x      = (const float*)d_in[0];
    const int*   ei     = (const int*)  d_in[1];
    const int*   et     = (const int*)  d_in[2];
    const float* W_in   = (const float*)d_in[3];
    const float* b_in   = (const float*)d_in[4];
    const float* W_rel  = (const float*)d_in[5];
    const float* W_gate = (const float*)d_in[6];
    const float* b_gate = (const float*)d_in[7];
    const float* W_att  = (const float*)d_in[8];
    const float* b_att  = (const float*)d_in[9];
    const float* ln_g   = (const float*)d_in[10];
    const float* ln_b   = (const float*)d_in[11];
    const float* W_out  = (const float*)d_in[12];
    const float* b_out  = (const float*)d_in[13];
    float* out = (float*)d_out;

    float *hbuf, *sprep;
    void *gatep, *prodp;
    cudaGetSymbolAddress((void**)&hbuf,  g_h);
    cudaGetSymbolAddress((void**)&sprep, g_spre);
    cudaGetSymbolAddress(&gatep, g_gate);
    cudaGetSymbolAddress(&prodp, g_prod);
    float* h0p = hbuf;
    float* h1p = hbuf + (size_t)NN * HH;

    cudaFuncSetAttribute(gemm64k, cudaFuncAttributeMaxDynamicSharedMemorySize, GEMM_SMEM);
    cudaFuncSetAttribute(gemmbf,  cudaFuncAttributeMaxDynamicSharedMemorySize, GEMMBF_SMEM);

    static cudaStream_t s2 = nullptr;
    static cudaEvent_t evF = nullptr, evG = nullptr, evC = nullptr;
    if (!s2) {
        cudaStreamCreateWithFlags(&s2, cudaStreamNonBlocking);
        cudaEventCreateWithFlags(&evF, cudaEventDisableTiming);
        cudaEventCreateWithFlags(&evG, cudaEventDisableTiming);
        cudaEventCreateWithFlags(&evC, cudaEventDisableTiming);
    }

    // fork: CSR build on s2, input projection on main
    cudaEventRecord(evF, 0);
    cudaStreamWaitEvent(s2, evF, 0);
    zerodeg_k<<<(NN + 255) / 256, 256, 0, s2>>>();
    hist_k<<<(EE + 255) / 256, 256, 0, s2>>>(ei);
    scan_k<<<1, 1024, 0, s2>>>();
    fill_k<<<(EE + 255) / 256, 256, 0, s2>>>(ei, et);
    cudaEventRecord(evC, s2);

    gemm64k<<<dim3((NN + 127) / 128, 1), 128, GEMM_SMEM>>>(x, 64, W_in, b_in, h0p, 64, NN, 0, 1);

    float* hc = h0p;
    float* hn = h1p;
    for (int layer = 0; layer < LL; layer++) {
        // fork: gate GEMM (bf16 split, fp16 out) on s2
        cudaEventRecord(evF, 0);
        cudaStreamWaitEvent(s2, evF, 0);
        gemmbf<<<dim3((NN + 127) / 128, 8), 128, GEMMBF_SMEM, s2>>>(hc, 64, W_gate, nullptr, gatep, 512, NN, 0, 0, 1);
        cudaEventRecord(evG, s2);

        // main: edge chain
        attproj_k<<<(NN + 15) / 16, 256>>>(hc, W_att);
        if (layer == 0) cudaStreamWaitEvent(0, evC, 0);
        scoreexp_k<<<(EE + 255) / 256, 256>>>(b_att);
        aggscatter_k<<<(NN + 7) / 8, 256>>>(hc);
        // relgemm (bf16 split, batched, fp16 out)
        gemmbf<<<dim3((NN + 127) / 128, 8), 128, GEMMBF_SMEM>>>(sprep, 512, W_rel, nullptr, prodp, 512, NN, 1, 0, 1);

        cudaStreamWaitEvent(0, evG, 0);
        combine_k<<<(NN + 7) / 8, 256>>>(hc, hn, b_gate, ln_g + layer * 64, ln_b + layer * 64);
        float* tmp = hc; hc = hn; hn = tmp;
    }

    gemm64k<<<dim3((NN + 127) / 128, 1), 128, GEMM_SMEM>>>(hc, 64, W_out, b_out, out, 64, NN, 0, 0);
}

// round 16
// speedup vs baseline: 1.1866x; 1.0124x over previous
#include <cuda_runtime.h>
#include <cuda_bf16.h>
#include <cuda_fp16.h>
#include <cstdint>

// ---------------- problem constants ----------------
#define NN 50000
#define EE 800000
#define HH 64
#define RR 8
#define LL 3
#define LN_EPS 1e-5f
#define NEG_SLOPE 0.2f

// ---------------- device scratch ----------------
__device__ float g_h[2 * NN * HH];          // ping-pong node features
__device__ __half g_prod[(size_t)NN * 512]; // relgemm output (fp16)
__device__ __half g_gate[(size_t)NN * 512]; // gate pre-activation (fp16)
__device__ __half g_spre[(size_t)NN * 512]; // att-weighted h sums (fp16)
__device__ float g_ap[NN * 16];             // attention projections
__device__ float g_exc[EE];                 // exp(score) in CSR order
__device__ float g_denom[RR];
__device__ int g_deg[NN];
__device__ int g_off[NN + 1];
__device__ int g_pos[NN];
__device__ int g_csrc[EE];                  // (src<<3)|et in CSR order
__device__ int g_cdst[EE];                  // dst in CSR order

// ---------------- fp32 K=64 SGEMM (in/out projections) ----------------
#define AS_STR 132
#define BS_STR 72
#define GEMM_SMEM ((64 * AS_STR + 64 * BS_STR) * 4)

__global__ __launch_bounds__(128)
void gemm64k(const float* __restrict__ A, int lda,
             const float* __restrict__ B,
             const float* __restrict__ bias, float* __restrict__ C, int ldc,
             int M, int batched, int act)
{
    extern __shared__ float smem[];
    float (*As)[AS_STR] = reinterpret_cast<float (*)[AS_STR]>(smem);
    float (*Bs)[BS_STR] = reinterpret_cast<float (*)[BS_STR]>(smem + 64 * AS_STR);

    const int tid = threadIdx.x;
    const int rowBase = blockIdx.x * 128;
    const int colBase = blockIdx.y * 64;
    const int aoff = batched ? colBase : 0;

    #pragma unroll
    for (int i = 0; i < 16; i++) {
        int f = tid + i * 128;
        int r = f >> 4;
        int kq = (f & 15) << 2;
        int gr = rowBase + r;
        float4 v = make_float4(0.f, 0.f, 0.f, 0.f);
        if (gr < M) v = *reinterpret_cast<const float4*>(A + (size_t)gr * lda + aoff + kq);
        As[kq + 0][r] = v.x; As[kq + 1][r] = v.y; As[kq + 2][r] = v.z; As[kq + 3][r] = v.w;
    }
    #pragma unroll
    for (int i = 0; i < 8; i++) {
        int f = tid + i * 128;
        int j = f >> 4;
        int kq = (f & 15) << 2;
        const float* brow = batched ? (B + (size_t)colBase * 64 + j * 64)
                                    : (B + (size_t)(colBase + j) * 64);
        float4 v = *reinterpret_cast<const float4*>(brow + kq);
        Bs[kq + 0][j] = v.x; Bs[kq + 1][j] = v.y; Bs[kq + 2][j] = v.z; Bs[kq + 3][j] = v.w;
    }
    __syncthreads();

    const int tx = tid & 7;
    const int ty = tid >> 3;

    unsigned long long acc[8][4];
    #pragma unroll
    for (int i = 0; i < 8; i++)
        #pragma unroll
        for (int j = 0; j < 4; j++) acc[i][j] = 0ULL;

    #pragma unroll
    for (int k = 0; k < 64; k++) {
        const float4* ap = reinterpret_cast<const float4*>(&As[k][ty * 8]);
        float4 a03 = ap[0], a47 = ap[1];
        float a[8] = {a03.x, a03.y, a03.z, a03.w, a47.x, a47.y, a47.z, a47.w};
        const ulonglong2* bp = reinterpret_cast<const ulonglong2*>(&Bs[k][tx * 8]);
        ulonglong2 bb0 = bp[0], bb1 = bp[1];
        unsigned long long b2[4] = {bb0.x, bb0.y, bb1.x, bb1.y};
        #pragma unroll
        for (int i = 0; i < 8; i++) {
            unsigned long long a2;
            asm("mov.b64 %0, {%1, %1};" : "=l"(a2) : "f"(a[i]));
            #pragma unroll
            for (int j = 0; j < 4; j++)
                asm("fma.rn.f32x2 %0, %1, %2, %0;" : "+l"(acc[i][j]) : "l"(a2), "l"(b2[j]));
        }
    }

    #pragma unroll
    for (int i = 0; i < 8; i++) {
        int gr = rowBase + ty * 8 + i;
        if (gr >= M) continue;
        #pragma unroll
        for (int j = 0; j < 4; j++) {
            float lo, hi;
            asm("mov.b64 {%0, %1}, %2;" : "=f"(lo), "=f"(hi) : "l"(acc[i][j]));
            int col = colBase + tx * 8 + 2 * j;
            if (bias) { lo += bias[col]; hi += bias[col + 1]; }
            if (act == 1) { lo = fmaxf(lo, 0.f); hi = fmaxf(hi, 0.f); }
            *reinterpret_cast<float2*>(C + (size_t)gr * ldc + col) = make_float2(lo, hi);
        }
    }
}

// ================= bf16 split-precision mma.sync GEMM =================
// half_out: C is __half; half_in: A is __half (converted to fp32 before split).
#define BF_STR 72
#define SA_HI 0
#define SA_LO (128 * BF_STR * 2)
#define SB_HI (SA_LO + 128 * BF_STR * 2)
#define SB_LO (SB_HI + 64 * BF_STR * 2)
#define GEMMBF_SMEM (SB_LO + 64 * BF_STR * 2)

__device__ __forceinline__ uint32_t smem_u32(const void* p) {
    uint32_t a;
    asm("{ .reg .u64 t; cvta.to.shared.u64 t, %1; cvt.u32.u64 %0, t; }" : "=r"(a) : "l"(p));
    return a;
}
__device__ __forceinline__ uint32_t pack_bf2(float x, float y) {
    __nv_bfloat162 t = __floats2bfloat162_rn(x, y);
    return *reinterpret_cast<uint32_t*>(&t);
}

#define LDSM_X4(r0, r1, r2, r3, addr) \
    asm volatile("ldmatrix.sync.aligned.m8n8.x4.shared.b16 {%0,%1,%2,%3}, [%4];" \
                 : "=r"(r0), "=r"(r1), "=r"(r2), "=r"(r3) : "r"(addr))
#define LDSM_X4T(r0, r1, r2, r3, addr) \
    asm volatile("ldmatrix.sync.aligned.m8n8.x4.trans.shared.b16 {%0,%1,%2,%3}, [%4];" \
                 : "=r"(r0), "=r"(r1), "=r"(r2), "=r"(r3) : "r"(addr))
#define MMA_BF(c, a, b0, b1) \
    asm volatile("mma.sync.aligned.m16n8k16.row.col.f32.bf16.bf16.f32 " \
                 "{%0,%1,%2,%3},{%4,%5,%6,%7},{%8,%9},{%0,%1,%2,%3};" \
                 : "+f"((c)[0]), "+f"((c)[1]), "+f"((c)[2]), "+f"((c)[3]) \
                 : "r"((a)[0]), "r"((a)[1]), "r"((a)[2]), "r"((a)[3]), "r"(b0), "r"(b1))

__global__ __launch_bounds__(128)
void gemmbf(const void* __restrict__ Av, int lda,
            const float* __restrict__ B,
            const float* __restrict__ bias, void* __restrict__ Cv, int ldc,
            int M, int batched, int act, int half_out, int half_in)
{
    extern __shared__ float smem[];
    char* smemc = reinterpret_cast<char*>(smem);
    __nv_bfloat16* Ahi = reinterpret_cast<__nv_bfloat16*>(smemc + SA_HI);
    __nv_bfloat16* Alo = reinterpret_cast<__nv_bfloat16*>(smemc + SA_LO);
    __nv_bfloat16* Bhi = reinterpret_cast<__nv_bfloat16*>(smemc + SB_HI);
    __nv_bfloat16* Blo = reinterpret_cast<__nv_bfloat16*>(smemc + SB_LO);

    const int tid = threadIdx.x, lane = tid & 31, warp = tid >> 5;
    const int rowBase = blockIdx.x * 128;
    const int colBase = blockIdx.y * 64;
    const int aoff = batched ? colBase : 0;

    // ---- stage A (128x64) -> bf16 hi/lo ----
    #pragma unroll
    for (int i = 0; i < 16; i++) {
        int idx4 = tid + i * 128;
        int row = idx4 >> 4;
        int kq = (idx4 & 15) << 2;
        int gr = rowBase + row;
        float4 v = make_float4(0.f, 0.f, 0.f, 0.f);
        if (gr < M) {
            if (half_in) {
                const __half* Ah = reinterpret_cast<const __half*>(Av);
                uint2 u = *reinterpret_cast<const uint2*>(Ah + (size_t)gr * lda + aoff + kq);
                float2 a01 = __half22float2(*reinterpret_cast<__half2*>(&u.x));
                float2 a23 = __half22float2(*reinterpret_cast<__half2*>(&u.y));
                v = make_float4(a01.x, a01.y, a23.x, a23.y);
            } else {
                const float* Af = reinterpret_cast<const float*>(Av);
                v = *reinterpret_cast<const float4*>(Af + (size_t)gr * lda + aoff + kq);
            }
        }
        float hx = __bfloat162float(__float2bfloat16_rn(v.x));
        float hy = __bfloat162float(__float2bfloat16_rn(v.y));
        float hz = __bfloat162float(__float2bfloat16_rn(v.z));
        float hw = __bfloat162float(__float2bfloat16_rn(v.w));
        uint32_t* ph = reinterpret_cast<uint32_t*>(&Ahi[row * BF_STR + kq]);
        uint32_t* pl = reinterpret_cast<uint32_t*>(&Alo[row * BF_STR + kq]);
        ph[0] = pack_bf2(hx, hy); ph[1] = pack_bf2(hz, hw);
        pl[0] = pack_bf2(v.x - hx, v.y - hy); pl[1] = pack_bf2(v.z - hz, v.w - hw);
    }
    // ---- stage B (64x64) ----
    #pragma unroll
    for (int i = 0; i < 8; i++) {
        int idx4 = tid + i * 128;
        int row = idx4 >> 4;
        int kq = (idx4 & 15) << 2;
        const float* brow = batched ? (B + (size_t)colBase * 64 + row * 64)
                                    : (B + (size_t)(colBase + row) * 64);
        float4 v = *reinterpret_cast<const float4*>(brow + kq);
        float hx = __bfloat162float(__float2bfloat16_rn(v.x));
        float hy = __bfloat162float(__float2bfloat16_rn(v.y));
        float hz = __bfloat162float(__float2bfloat16_rn(v.z));
        float hw = __bfloat162float(__float2bfloat16_rn(v.w));
        uint32_t* ph = reinterpret_cast<uint32_t*>(&Bhi[row * BF_STR + kq]);
        uint32_t* pl = reinterpret_cast<uint32_t*>(&Blo[row * BF_STR + kq]);
        ph[0] = pack_bf2(hx, hy); ph[1] = pack_bf2(hz, hw);
        pl[0] = pack_bf2(v.x - hx, v.y - hy); pl[1] = pack_bf2(v.z - hz, v.w - hw);
    }
    __syncthreads();

    uint32_t sbase = smem_u32(smemc);
    uint32_t aRow = warp * 32 + (lane & 15);
    uint32_t aCol = (lane >> 4) << 3;
    uint32_t aHiAddr = sbase + SA_HI + (aRow * BF_STR + aCol) * 2;
    uint32_t aLoAddr = sbase + SA_LO + (aRow * BF_STR + aCol) * 2;
    uint32_t bN = (lane & 7) + ((lane >> 4) << 3);
    uint32_t bK = ((lane >> 3) & 1) << 3;
    uint32_t bHiAddr = sbase + SB_HI + (bN * BF_STR + bK) * 2;
    uint32_t bLoAddr = sbase + SB_LO + (bN * BF_STR + bK) * 2;

    float c[2][8][4];
    #pragma unroll
    for (int a = 0; a < 2; a++)
        #pragma unroll
        for (int n = 0; n < 8; n++)
            #pragma unroll
            for (int j = 0; j < 4; j++) c[a][n][j] = 0.f;

    #pragma unroll
    for (int ks = 0; ks < 4; ks++) {
        uint32_t ka = ks * 32;
        uint32_t ah[2][4], al[2][4];
        LDSM_X4(ah[0][0], ah[0][1], ah[0][2], ah[0][3], aHiAddr + ka);
        LDSM_X4(ah[1][0], ah[1][1], ah[1][2], ah[1][3], aHiAddr + 16 * BF_STR * 2 + ka);
        LDSM_X4(al[0][0], al[0][1], al[0][2], al[0][3], aLoAddr + ka);
        LDSM_X4(al[1][0], al[1][1], al[1][2], al[1][3], aLoAddr + 16 * BF_STR * 2 + ka);
        #pragma unroll
        for (int p = 0; p < 4; p++) {
            uint32_t bo = p * 16 * BF_STR * 2 + ka;
            uint32_t bh0, bh1, bh2, bh3, bl0, bl1, bl2, bl3;
            LDSM_X4T(bh0, bh1, bh2, bh3, bHiAddr + bo);
            LDSM_X4T(bl0, bl1, bl2, bl3, bLoAddr + bo);
            #pragma unroll
            for (int a = 0; a < 2; a++) {
                MMA_BF(c[a][2 * p],     ah[a], bh0, bh1);
                MMA_BF(c[a][2 * p],     ah[a], bl0, bl1);
                MMA_BF(c[a][2 * p],     al[a], bh0, bh1);
                MMA_BF(c[a][2 * p + 1], ah[a], bh2, bh3);
                MMA_BF(c[a][2 * p + 1], ah[a], bl2, bl3);
                MMA_BF(c[a][2 * p + 1], al[a], bh2, bh3);
            }
        }
    }

    #pragma unroll
    for (int a = 0; a < 2; a++) {
        int gr0 = rowBase + warp * 32 + a * 16 + (lane >> 2);
        #pragma unroll
        for (int n = 0; n < 8; n++) {
            int col = colBase + n * 8 + (lane & 3) * 2;
            float lo0 = c[a][n][0], hi0 = c[a][n][1];
            float lo1 = c[a][n][2], hi1 = c[a][n][3];
            if (bias) {
                float bx = bias[col], by = bias[col + 1];
                lo0 += bx; hi0 += by; lo1 += bx; hi1 += by;
            }
            if (act == 1) {
                lo0 = fmaxf(lo0, 0.f); hi0 = fmaxf(hi0, 0.f);
                lo1 = fmaxf(lo1, 0.f); hi1 = fmaxf(hi1, 0.f);
            }
            if (half_out) {
                __half* Ch = reinterpret_cast<__half*>(Cv);
                if (gr0 < M)
                    *reinterpret_cast<__half2*>(Ch + (size_t)gr0 * ldc + col) = __floats2half2_rn(lo0, hi0);
                if (gr0 + 8 < M)
                    *reinterpret_cast<__half2*>(Ch + (size_t)(gr0 + 8) * ldc + col) = __floats2half2_rn(lo1, hi1);
            } else {
                float* Cf = reinterpret_cast<float*>(Cv);
                if (gr0 < M)
                    *reinterpret_cast<float2*>(Cf + (size_t)gr0 * ldc + col) = make_float2(lo0, hi0);
                if (gr0 + 8 < M)
                    *reinterpret_cast<float2*>(Cf + (size_t)(gr0 + 8) * ldc + col) = make_float2(lo1, hi1);
            }
        }
    }
}

// ---------------- CSR build ----------------
__global__ __launch_bounds__(256)
void zerodeg_k()
{
    int i = blockIdx.x * 256 + threadIdx.x;
    if (i < NN) g_deg[i] = 0;
}

__global__ __launch_bounds__(256)
void hist_k(const int* __restrict__ ei)
{
    int e = blockIdx.x * 256 + threadIdx.x;
    if (e < EE) atomicAdd(&g_deg[ei[EE + e]], 1);
}

__global__ __launch_bounds__(1024)
void scan_k()
{
    __shared__ int s[1024];
    __shared__ int carry_s;
    int tid = threadIdx.x;
    if (tid == 0) carry_s = 0;
    __syncthreads();
    for (int base = 0; base < NN; base += 4096) {
        int i0 = base + tid * 4;
        int v0 = (i0 + 0 < NN) ? g_deg[i0 + 0] : 0;
        int v1 = (i0 + 1 < NN) ? g_deg[i0 + 1] : 0;
        int v2 = (i0 + 2 < NN) ? g_deg[i0 + 2] : 0;
        int v3 = (i0 + 3 < NN) ? g_deg[i0 + 3] : 0;
        int tsum = v0 + v1 + v2 + v3;
        int val = tsum;
        s[tid] = val;
        __syncthreads();
        #pragma unroll
        for (int off = 1; off < 1024; off <<= 1) {
            int t = (tid >= off) ? s[tid - off] : 0;
            __syncthreads();
            val += t;
            s[tid] = val;
            __syncthreads();
        }
        int carry = carry_s;
        int o0 = carry + val - tsum;
        int o1 = o0 + v0, o2 = o1 + v1, o3 = o2 + v2;
        if (i0 + 0 < NN) { g_off[i0 + 0] = o0; g_pos[i0 + 0] = o0; }
        if (i0 + 1 < NN) { g_off[i0 + 1] = o1; g_pos[i0 + 1] = o1; }
        if (i0 + 2 < NN) { g_off[i0 + 2] = o2; g_pos[i0 + 2] = o2; }
        if (i0 + 3 < NN) { g_off[i0 + 3] = o3; g_pos[i0 + 3] = o3; }
        __syncthreads();
        if (tid == 1023) carry_s = carry + val;
        __syncthreads();
    }
    if (tid == 0) g_off[NN] = EE;
}

__global__ __launch_bounds__(256)
void fill_k(const int* __restrict__ ei, const int* __restrict__ et)
{
    int e = blockIdx.x * 256 + threadIdx.x;
    if (e >= EE) return;
    int dst = ei[EE + e];
    int p = atomicAdd(&g_pos[dst], 1);
    g_csrc[p] = (ei[e] << 3) | et[e];
    g_cdst[p] = dst;
}

// ---------------- attention projections ----------------
__global__ __launch_bounds__(256)
void attproj_k(const float* __restrict__ h, const float* __restrict__ W_att)
{
    __shared__ float hs[16][65];
    __shared__ float ws[16][65];
    int tid = threadIdx.x;
    int nodeBase = blockIdx.x * 16;
    for (int i = tid; i < 16 * 64; i += 256) {
        int o = i >> 6, c = i & 63;
        ws[o][c] = W_att[(o & 7) * 128 + ((o >> 3) << 6) + c];
        int n = nodeBase + o;
        hs[o][c] = (n < NN) ? h[n * 64 + c] : 0.f;
    }
    __syncthreads();
    int nd = tid >> 4, o = tid & 15;
    float s = 0.f;
    #pragma unroll
    for (int c = 0; c < 64; c++) s += hs[nd][c] * ws[o][c];
    int n = nodeBase + nd;
    if (n < NN) g_ap[n * 16 + o] = s;
    if (blockIdx.x == 0 && tid < RR) g_denom[tid] = 0.f;
}

// ---------------- scores + exp + denom, CSR order ----------
__global__ __launch_bounds__(256)
void scoreexp_k(const float* __restrict__ b_att)
{
    __shared__ float ssum[RR];
    int tid = threadIdx.x;
    if (tid < RR) ssum[tid] = 0.f;
    __syncthreads();
    int j = blockIdx.x * 256 + tid;
    if (j < EE) {
        int pk = g_csrc[j];
        int t = pk & 7;
        int s = pk >> 3;
        int d = g_cdst[j];
        float sc = g_ap[s * 16 + t] + g_ap[d * 16 + 8 + t] + b_att[t];
        sc = (sc > 0.f) ? sc : NEG_SLOPE * sc;
        float ex = __expf(sc);
        g_exc[j] = ex;
        atomicAdd(&ssum[t], ex);
    }
    __syncthreads();
    if (tid < RR) atomicAdd(&g_denom[tid], ssum[tid]);
}

// ---------------- aggregate att-weighted h[src] per (dst, r) ----------------
__global__ __launch_bounds__(256)
void aggscatter_k(const float* __restrict__ h)
{
    __shared__ float sden[RR];
    int tid = threadIdx.x;
    if (tid < RR) sden[tid] = 1.f / g_denom[tid];
    __syncthreads();

    int warp = tid >> 5, lane = tid & 31;
    int half = lane >> 4;
    int c4 = (lane & 15) * 4;
    int n = blockIdx.x * 8 + warp;
    if (n >= NN) return;

    float4 acc[8];
    #pragma unroll
    for (int r = 0; r < 8; r++) acc[r] = make_float4(0.f, 0.f, 0.f, 0.f);

    int beg = g_off[n], end = g_off[n + 1];
    for (int b = beg; b < end; b += 8) {
        int pk[4]; float at[4];
        #pragma unroll
        for (int i = 0; i < 4; i++) {
            int j = b + 2 * i + half;
            int jc = (j < end) ? j : beg;
            pk[i] = g_csrc[jc];
            float ex = g_exc[jc];
            at[i] = (j < end) ? ex * sden[pk[i] & 7] : 0.f;
        }
        float4 v[4];
        #pragma unroll
        for (int i = 0; i < 4; i++)
            v[i] = *reinterpret_cast<const float4*>(&h[(pk[i] >> 3) * 64 + c4]);
        #pragma unroll
        for (int i = 0; i < 4; i++) {
            int er = pk[i] & 7;
            #pragma unroll
            for (int r = 0; r < 8; r++)
                if (er == r) {
                    acc[r].x += at[i] * v[i].x; acc[r].y += at[i] * v[i].y;
                    acc[r].z += at[i] * v[i].z; acc[r].w += at[i] * v[i].w;
                }
        }
    }

    #pragma unroll
    for (int r = 0; r < 8; r++) {
        acc[r].x += __shfl_xor_sync(0xffffffffu, acc[r].x, 16);
        acc[r].y += __shfl_xor_sync(0xffffffffu, acc[r].y, 16);
        acc[r].z += __shfl_xor_sync(0xffffffffu, acc[r].z, 16);
        acc[r].w += __shfl_xor_sync(0xffffffffu, acc[r].w, 16);
    }

    if (half == 0) {
        size_t base = (size_t)n * 512;
        #pragma unroll
        for (int r = 0; r < 8; r++) {
            __half2 p0 = __floats2half2_rn(acc[r].x, acc[r].y);
            __half2 p1 = __floats2half2_rn(acc[r].z, acc[r].w);
            uint2 u;
            u.x = *reinterpret_cast<uint32_t*>(&p0);
            u.y = *reinterpret_cast<uint32_t*>(&p1);
            *reinterpret_cast<uint2*>(&g_spre[base + r * 64 + c4]) = u;
        }
    }
}

// ---------------- gate*prod mean + residual + LN + relu (fp16 gate/prod) ----
__global__ __launch_bounds__(256)
void combine_k(const float* __restrict__ hin, float* __restrict__ hout,
               const float* __restrict__ b_gate,
               const float* __restrict__ gamma, const float* __restrict__ beta)
{
    int tid = threadIdx.x;
    int warp = tid >> 5, lane = tid & 31;
    int half = lane >> 4;
    int c4 = (lane & 15) * 4;
    int n = blockIdx.x * 8 + warp;
    if (n >= NN) return;

    size_t base = (size_t)n * 512;
    float4 hx = make_float4(0.f, 0.f, 0.f, 0.f);
    #pragma unroll
    for (int rr = 0; rr < 4; rr++) {
        int r = 2 * rr + half;
        int o = r * 64 + c4;
        uint2 gu = *reinterpret_cast<const uint2*>(&g_gate[base + o]);
        uint2 pu = *reinterpret_cast<const uint2*>(&g_prod[base + o]);
        float2 g01 = __half22float2(*reinterpret_cast<__half2*>(&gu.x));
        float2 g23 = __half22float2(*reinterpret_cast<__half2*>(&gu.y));
        float2 p01 = __half22float2(*reinterpret_cast<__half2*>(&pu.x));
        float2 p23 = __half22float2(*reinterpret_cast<__half2*>(&pu.y));
        float4 bg = *reinterpret_cast<const float4*>(&b_gate[o]);
        hx.x += p01.x / (1.f + __expf(-(g01.x + bg.x)));
        hx.y += p01.y / (1.f + __expf(-(g01.y + bg.y)));
        hx.z += p23.x / (1.f + __expf(-(g23.x + bg.z)));
        hx.w += p23.y / (1.f + __expf(-(g23.y + bg.w)));
    }
    hx.x += __shfl_xor_sync(0xffffffffu, hx.x, 16);
    hx.y += __shfl_xor_sync(0xffffffffu, hx.y, 16);
    hx.z += __shfl_xor_sync(0xffffffffu, hx.z, 16);
    hx.w += __shfl_xor_sync(0xffffffffu, hx.w, 16);

    float4 hv = *reinterpret_cast<const float4*>(&hin[(size_t)n * 64 + c4]);
    float h0 = hv.x + hx.x * 0.125f;
    float h1 = hv.y + hx.y * 0.125f;
    float h2 = hv.z + hx.z * 0.125f;
    float h3 = hv.w + hx.w * 0.125f;

    float s = h0 + h1 + h2 + h3;
    #pragma unroll
    for (int o = 8; o > 0; o >>= 1) s += __shfl_xor_sync(0xffffffffu, s, o);
    float mu = s * (1.f / 64.f);
    float d0 = h0 - mu, d1 = h1 - mu, d2 = h2 - mu, d3 = h3 - mu;
    float v = d0 * d0 + d1 * d1 + d2 * d2 + d3 * d3;
    #pragma unroll
    for (int o = 8; o > 0; o >>= 1) v += __shfl_xor_sync(0xffffffffu, v, o);
    float rs = rsqrtf(v * (1.f / 64.f) + LN_EPS);

    if (half == 0) {
        float4 gm = *reinterpret_cast<const float4*>(&gamma[c4]);
        float4 bt = *reinterpret_cast<const float4*>(&beta[c4]);
        float4 o4;
        o4.x = fmaxf(d0 * rs * gm.x + bt.x, 0.f);
        o4.y = fmaxf(d1 * rs * gm.y + bt.y, 0.f);
        o4.z = fmaxf(d2 * rs * gm.z + bt.z, 0.f);
        o4.w = fmaxf(d3 * rs * gm.w + bt.w, 0.f);
        *reinterpret_cast<float4*>(&hout[(size_t)n * 64 + c4]) = o4;
    }
}

// ---------------- launch ----------------
extern "C" void kernel_launch(void* const* d_in, const int* in_sizes, int n_in,
                              void* d_out, int out_size)
{
    const float* x      = (const float*)d_in[0];
    const int*   ei     = (const int*)  d_in[1];
    const int*   et     = (const int*)  d_in[2];
    const float* W_in   = (const float*)d_in[3];
    const float* b_in   = (const float*)d_in[4];
    const float* W_rel  = (const float*)d_in[5];
    const float* W_gate = (const float*)d_in[6];
    const float* b_gate = (const float*)d_in[7];
    const float* W_att  = (const float*)d_in[8];
    const float* b_att  = (const float*)d_in[9];
    const float* ln_g   = (const float*)d_in[10];
    const float* ln_b   = (const float*)d_in[11];
    const float* W_out  = (const float*)d_in[12];
    const float* b_out  = (const float*)d_in[13];
    float* out = (float*)d_out;

    float* hbuf;
    void *sprep, *gatep, *prodp;
    cudaGetSymbolAddress((void**)&hbuf, g_h);
    cudaGetSymbolAddress(&sprep, g_spre);
    cudaGetSymbolAddress(&gatep, g_gate);
    cudaGetSymbolAddress(&prodp, g_prod);
    float* h0p = hbuf;
    float* h1p = hbuf + (size_t)NN * HH;

    cudaFuncSetAttribute(gemm64k, cudaFuncAttributeMaxDynamicSharedMemorySize, GEMM_SMEM);
    cudaFuncSetAttribute(gemmbf,  cudaFuncAttributeMaxDynamicSharedMemorySize, GEMMBF_SMEM);

    static cudaStream_t s2 = nullptr;
    static cudaEvent_t evF = nullptr, evG = nullptr, evC = nullptr;
    if (!s2) {
        cudaStreamCreateWithFlags(&s2, cudaStreamNonBlocking);
        cudaEventCreateWithFlags(&evF, cudaEventDisableTiming);
        cudaEventCreateWithFlags(&evG, cudaEventDisableTiming);
        cudaEventCreateWithFlags(&evC, cudaEventDisableTiming);
    }

    // fork: CSR build on s2, input projection on main
    cudaEventRecord(evF, 0);
    cudaStreamWaitEvent(s2, evF, 0);
    zerodeg_k<<<(NN + 255) / 256, 256, 0, s2>>>();
    hist_k<<<(EE + 255) / 256, 256, 0, s2>>>(ei);
    scan_k<<<1, 1024, 0, s2>>>();
    fill_k<<<(EE + 255) / 256, 256, 0, s2>>>(ei, et);
    cudaEventRecord(evC, s2);

    gemm64k<<<dim3((NN + 127) / 128, 1), 128, GEMM_SMEM>>>(x, 64, W_in, b_in, h0p, 64, NN, 0, 1);

    float* hc = h0p;
    float* hn = h1p;
    for (int layer = 0; layer < LL; layer++) {
        // fork: gate GEMM (bf16 split, fp16 out) on s2
        cudaEventRecord(evF, 0);
        cudaStreamWaitEvent(s2, evF, 0);
        gemmbf<<<dim3((NN + 127) / 128, 8), 128, GEMMBF_SMEM, s2>>>(hc, 64, W_gate, nullptr, gatep, 512, NN, 0, 0, 1, 0);
        cudaEventRecord(evG, s2);

        // main: edge chain
        attproj_k<<<(NN + 15) / 16, 256>>>(hc, W_att);
        if (layer == 0) cudaStreamWaitEvent(0, evC, 0);
        scoreexp_k<<<(EE + 255) / 256, 256>>>(b_att);
        aggscatter_k<<<(NN + 7) / 8, 256>>>(hc);
        // relgemm (bf16 split, batched, fp16 in + fp16 out)
        gemmbf<<<dim3((NN + 127) / 128, 8), 128, GEMMBF_SMEM>>>(sprep, 512, W_rel, nullptr, prodp, 512, NN, 1, 0, 1, 1);

        cudaStreamWaitEvent(0, evG, 0);
        combine_k<<<(NN + 7) / 8, 256>>>(hc, hn, b_gate, ln_g + layer * 64, ln_b + layer * 64);
        float* tmp = hc; hc = hn; hn = tmp;
    }

    gemm64k<<<dim3((NN + 127) / 128, 1), 128, GEMM_SMEM>>>(hc, 64, W_out, b_out, out, 64, NN, 0, 0);
}

// round 17
// speedup vs baseline: 1.1974x; 1.0091x over previous
#include <cuda_runtime.h>
#include <cuda_bf16.h>
#include <cuda_fp16.h>
#include <cstdint>

// ---------------- problem constants ----------------
#define NN 50000
#define EE 800000
#define HH 64
#define RR 8
#define LL 3
#define LN_EPS 1e-5f
#define NEG_SLOPE 0.2f

// ---------------- device scratch ----------------
__device__ float g_h[2 * NN * HH];          // ping-pong node features (fp32 master)
__device__ __half g_h16[2 * NN * HH];       // fp16 mirror for gathers
__device__ __half g_prod[(size_t)NN * 512]; // relgemm output (fp16)
__device__ __half g_gate[(size_t)NN * 512]; // gate pre-activation (fp16)
__device__ __half g_spre[(size_t)NN * 512]; // att-weighted h sums (fp16)
__device__ float g_ap[NN * 16];             // attention projections
__device__ float g_exc[EE];                 // exp(score) in CSR order
__device__ float g_denom[RR];
__device__ int g_deg[NN];
__device__ int g_off[NN + 1];
__device__ int g_pos[NN];
__device__ int g_csrc[EE];                  // (src<<3)|et in CSR order
__device__ int g_cdst[EE];                  // dst in CSR order

// ---------------- fp32 K=64 SGEMM (in/out projections) ----------------
#define AS_STR 132
#define BS_STR 72
#define GEMM_SMEM ((64 * AS_STR + 64 * BS_STR) * 4)

__global__ __launch_bounds__(128)
void gemm64k(const float* __restrict__ A, int lda,
             const float* __restrict__ B,
             const float* __restrict__ bias, float* __restrict__ C, int ldc,
             int M, int batched, int act, __half* __restrict__ mirror)
{
    extern __shared__ float smem[];
    float (*As)[AS_STR] = reinterpret_cast<float (*)[AS_STR]>(smem);
    float (*Bs)[BS_STR] = reinterpret_cast<float (*)[BS_STR]>(smem + 64 * AS_STR);

    const int tid = threadIdx.x;
    const int rowBase = blockIdx.x * 128;
    const int colBase = blockIdx.y * 64;
    const int aoff = batched ? colBase : 0;

    #pragma unroll
    for (int i = 0; i < 16; i++) {
        int f = tid + i * 128;
        int r = f >> 4;
        int kq = (f & 15) << 2;
        int gr = rowBase + r;
        float4 v = make_float4(0.f, 0.f, 0.f, 0.f);
        if (gr < M) v = *reinterpret_cast<const float4*>(A + (size_t)gr * lda + aoff + kq);
        As[kq + 0][r] = v.x; As[kq + 1][r] = v.y; As[kq + 2][r] = v.z; As[kq + 3][r] = v.w;
    }
    #pragma unroll
    for (int i = 0; i < 8; i++) {
        int f = tid + i * 128;
        int j = f >> 4;
        int kq = (f & 15) << 2;
        const float* brow = batched ? (B + (size_t)colBase * 64 + j * 64)
                                    : (B + (size_t)(colBase + j) * 64);
        float4 v = *reinterpret_cast<const float4*>(brow + kq);
        Bs[kq + 0][j] = v.x; Bs[kq + 1][j] = v.y; Bs[kq + 2][j] = v.z; Bs[kq + 3][j] = v.w;
    }
    __syncthreads();

    const int tx = tid & 7;
    const int ty = tid >> 3;

    unsigned long long acc[8][4];
    #pragma unroll
    for (int i = 0; i < 8; i++)
        #pragma unroll
        for (int j = 0; j < 4; j++) acc[i][j] = 0ULL;

    #pragma unroll
    for (int k = 0; k < 64; k++) {
        const float4* ap = reinterpret_cast<const float4*>(&As[k][ty * 8]);
        float4 a03 = ap[0], a47 = ap[1];
        float a[8] = {a03.x, a03.y, a03.z, a03.w, a47.x, a47.y, a47.z, a47.w};
        const ulonglong2* bp = reinterpret_cast<const ulonglong2*>(&Bs[k][tx * 8]);
        ulonglong2 bb0 = bp[0], bb1 = bp[1];
        unsigned long long b2[4] = {bb0.x, bb0.y, bb1.x, bb1.y};
        #pragma unroll
        for (int i = 0; i < 8; i++) {
            unsigned long long a2;
            asm("mov.b64 %0, {%1, %1};" : "=l"(a2) : "f"(a[i]));
            #pragma unroll
            for (int j = 0; j < 4; j++)
                asm("fma.rn.f32x2 %0, %1, %2, %0;" : "+l"(acc[i][j]) : "l"(a2), "l"(b2[j]));
        }
    }

    #pragma unroll
    for (int i = 0; i < 8; i++) {
        int gr = rowBase + ty * 8 + i;
        if (gr >= M) continue;
        #pragma unroll
        for (int j = 0; j < 4; j++) {
            float lo, hi;
            asm("mov.b64 {%0, %1}, %2;" : "=f"(lo), "=f"(hi) : "l"(acc[i][j]));
            int col = colBase + tx * 8 + 2 * j;
            if (bias) { lo += bias[col]; hi += bias[col + 1]; }
            if (act == 1) { lo = fmaxf(lo, 0.f); hi = fmaxf(hi, 0.f); }
            *reinterpret_cast<float2*>(C + (size_t)gr * ldc + col) = make_float2(lo, hi);
            if (mirror)
                *reinterpret_cast<__half2*>(mirror + (size_t)gr * 64 + col) = __floats2half2_rn(lo, hi);
        }
    }
}

// ================= bf16 split-precision mma.sync GEMM =================
#define BF_STR 72
#define SA_HI 0
#define SA_LO (128 * BF_STR * 2)
#define SB_HI (SA_LO + 128 * BF_STR * 2)
#define SB_LO (SB_HI + 64 * BF_STR * 2)
#define GEMMBF_SMEM (SB_LO + 64 * BF_STR * 2)

__device__ __forceinline__ uint32_t smem_u32(const void* p) {
    uint32_t a;
    asm("{ .reg .u64 t; cvta.to.shared.u64 t, %1; cvt.u32.u64 %0, t; }" : "=r"(a) : "l"(p));
    return a;
}
__device__ __forceinline__ uint32_t pack_bf2(float x, float y) {
    __nv_bfloat162 t = __floats2bfloat162_rn(x, y);
    return *reinterpret_cast<uint32_t*>(&t);
}

#define LDSM_X4(r0, r1, r2, r3, addr) \
    asm volatile("ldmatrix.sync.aligned.m8n8.x4.shared.b16 {%0,%1,%2,%3}, [%4];" \
                 : "=r"(r0), "=r"(r1), "=r"(r2), "=r"(r3) : "r"(addr))
#define LDSM_X4T(r0, r1, r2, r3, addr) \
    asm volatile("ldmatrix.sync.aligned.m8n8.x4.trans.shared.b16 {%0,%1,%2,%3}, [%4];" \
                 : "=r"(r0), "=r"(r1), "=r"(r2), "=r"(r3) : "r"(addr))
#define MMA_BF(c, a, b0, b1) \
    asm volatile("mma.sync.aligned.m16n8k16.row.col.f32.bf16.bf16.f32 " \
                 "{%0,%1,%2,%3},{%4,%5,%6,%7},{%8,%9},{%0,%1,%2,%3};" \
                 : "+f"((c)[0]), "+f"((c)[1]), "+f"((c)[2]), "+f"((c)[3]) \
                 : "r"((a)[0]), "r"((a)[1]), "r"((a)[2]), "r"((a)[3]), "r"(b0), "r"(b1))

__global__ __launch_bounds__(128)
void gemmbf(const void* __restrict__ Av, int lda,
            const float* __restrict__ B,
            const float* __restrict__ bias, void* __restrict__ Cv, int ldc,
            int M, int batched, int act, int half_out, int half_in)
{
    extern __shared__ float smem[];
    char* smemc = reinterpret_cast<char*>(smem);
    __nv_bfloat16* Ahi = reinterpret_cast<__nv_bfloat16*>(smemc + SA_HI);
    __nv_bfloat16* Alo = reinterpret_cast<__nv_bfloat16*>(smemc + SA_LO);
    __nv_bfloat16* Bhi = reinterpret_cast<__nv_bfloat16*>(smemc + SB_HI);
    __nv_bfloat16* Blo = reinterpret_cast<__nv_bfloat16*>(smemc + SB_LO);

    const int tid = threadIdx.x, lane = tid & 31, warp = tid >> 5;
    const int rowBase = blockIdx.x * 128;
    const int colBase = blockIdx.y * 64;
    const int aoff = batched ? colBase : 0;

    #pragma unroll
    for (int i = 0; i < 16; i++) {
        int idx4 = tid + i * 128;
        int row = idx4 >> 4;
        int kq = (idx4 & 15) << 2;
        int gr = rowBase + row;
        float4 v = make_float4(0.f, 0.f, 0.f, 0.f);
        if (gr < M) {
            if (half_in) {
                const __half* Ah = reinterpret_cast<const __half*>(Av);
                uint2 u = *reinterpret_cast<const uint2*>(Ah + (size_t)gr * lda + aoff + kq);
                float2 a01 = __half22float2(*reinterpret_cast<__half2*>(&u.x));
                float2 a23 = __half22float2(*reinterpret_cast<__half2*>(&u.y));
                v = make_float4(a01.x, a01.y, a23.x, a23.y);
            } else {
                const float* Af = reinterpret_cast<const float*>(Av);
                v = *reinterpret_cast<const float4*>(Af + (size_t)gr * lda + aoff + kq);
            }
        }
        float hx = __bfloat162float(__float2bfloat16_rn(v.x));
        float hy = __bfloat162float(__float2bfloat16_rn(v.y));
        float hz = __bfloat162float(__float2bfloat16_rn(v.z));
        float hw = __bfloat162float(__float2bfloat16_rn(v.w));
        uint32_t* ph = reinterpret_cast<uint32_t*>(&Ahi[row * BF_STR + kq]);
        uint32_t* pl = reinterpret_cast<uint32_t*>(&Alo[row * BF_STR + kq]);
        ph[0] = pack_bf2(hx, hy); ph[1] = pack_bf2(hz, hw);
        pl[0] = pack_bf2(v.x - hx, v.y - hy); pl[1] = pack_bf2(v.z - hz, v.w - hw);
    }
    #pragma unroll
    for (int i = 0; i < 8; i++) {
        int idx4 = tid + i * 128;
        int row = idx4 >> 4;
        int kq = (idx4 & 15) << 2;
        const float* brow = batched ? (B + (size_t)colBase * 64 + row * 64)
                                    : (B + (size_t)(colBase + row) * 64);
        float4 v = *reinterpret_cast<const float4*>(brow + kq);
        float hx = __bfloat162float(__float2bfloat16_rn(v.x));
        float hy = __bfloat162float(__float2bfloat16_rn(v.y));
        float hz = __bfloat162float(__float2bfloat16_rn(v.z));
        float hw = __bfloat162float(__float2bfloat16_rn(v.w));
        uint32_t* ph = reinterpret_cast<uint32_t*>(&Bhi[row * BF_STR + kq]);
        uint32_t* pl = reinterpret_cast<uint32_t*>(&Blo[row * BF_STR + kq]);
        ph[0] = pack_bf2(hx, hy); ph[1] = pack_bf2(hz, hw);
        pl[0] = pack_bf2(v.x - hx, v.y - hy); pl[1] = pack_bf2(v.z - hz, v.w - hw);
    }
    __syncthreads();

    uint32_t sbase = smem_u32(smemc);
    uint32_t aRow = warp * 32 + (lane & 15);
    uint32_t aCol = (lane >> 4) << 3;
    uint32_t aHiAddr = sbase + SA_HI + (aRow * BF_STR + aCol) * 2;
    uint32_t aLoAddr = sbase + SA_LO + (aRow * BF_STR + aCol) * 2;
    uint32_t bN = (lane & 7) + ((lane >> 4) << 3);
    uint32_t bK = ((lane >> 3) & 1) << 3;
    uint32_t bHiAddr = sbase + SB_HI + (bN * BF_STR + bK) * 2;
    uint32_t bLoAddr = sbase + SB_LO + (bN * BF_STR + bK) * 2;

    float c[2][8][4];
    #pragma unroll
    for (int a = 0; a < 2; a++)
        #pragma unroll
        for (int n = 0; n < 8; n++)
            #pragma unroll
            for (int j = 0; j < 4; j++) c[a][n][j] = 0.f;

    #pragma unroll
    for (int ks = 0; ks < 4; ks++) {
        uint32_t ka = ks * 32;
        uint32_t ah[2][4], al[2][4];
        LDSM_X4(ah[0][0], ah[0][1], ah[0][2], ah[0][3], aHiAddr + ka);
        LDSM_X4(ah[1][0], ah[1][1], ah[1][2], ah[1][3], aHiAddr + 16 * BF_STR * 2 + ka);
        LDSM_X4(al[0][0], al[0][1], al[0][2], al[0][3], aLoAddr + ka);
        LDSM_X4(al[1][0], al[1][1], al[1][2], al[1][3], aLoAddr + 16 * BF_STR * 2 + ka);
        #pragma unroll
        for (int p = 0; p < 4; p++) {
            uint32_t bo = p * 16 * BF_STR * 2 + ka;
            uint32_t bh0, bh1, bh2, bh3, bl0, bl1, bl2, bl3;
            LDSM_X4T(bh0, bh1, bh2, bh3, bHiAddr + bo);
            LDSM_X4T(bl0, bl1, bl2, bl3, bLoAddr + bo);
            #pragma unroll
            for (int a = 0; a < 2; a++) {
                MMA_BF(c[a][2 * p],     ah[a], bh0, bh1);
                MMA_BF(c[a][2 * p],     ah[a], bl0, bl1);
                MMA_BF(c[a][2 * p],     al[a], bh0, bh1);
                MMA_BF(c[a][2 * p + 1], ah[a], bh2, bh3);
                MMA_BF(c[a][2 * p + 1], ah[a], bl2, bl3);
                MMA_BF(c[a][2 * p + 1], al[a], bh2, bh3);
            }
        }
    }

    #pragma unroll
    for (int a = 0; a < 2; a++) {
        int gr0 = rowBase + warp * 32 + a * 16 + (lane >> 2);
        #pragma unroll
        for (int n = 0; n < 8; n++) {
            int col = colBase + n * 8 + (lane & 3) * 2;
            float lo0 = c[a][n][0], hi0 = c[a][n][1];
            float lo1 = c[a][n][2], hi1 = c[a][n][3];
            if (bias) {
                float bx = bias[col], by = bias[col + 1];
                lo0 += bx; hi0 += by; lo1 += bx; hi1 += by;
            }
            if (act == 1) {
                lo0 = fmaxf(lo0, 0.f); hi0 = fmaxf(hi0, 0.f);
                lo1 = fmaxf(lo1, 0.f); hi1 = fmaxf(hi1, 0.f);
            }
            if (half_out) {
                __half* Ch = reinterpret_cast<__half*>(Cv);
                if (gr0 < M)
                    *reinterpret_cast<__half2*>(Ch + (size_t)gr0 * ldc + col) = __floats2half2_rn(lo0, hi0);
                if (gr0 + 8 < M)
                    *reinterpret_cast<__half2*>(Ch + (size_t)(gr0 + 8) * ldc + col) = __floats2half2_rn(lo1, hi1);
            } else {
                float* Cf = reinterpret_cast<float*>(Cv);
                if (gr0 < M)
                    *reinterpret_cast<float2*>(Cf + (size_t)gr0 * ldc + col) = make_float2(lo0, hi0);
                if (gr0 + 8 < M)
                    *reinterpret_cast<float2*>(Cf + (size_t)(gr0 + 8) * ldc + col) = make_float2(lo1, hi1);
            }
        }
    }
}

// ---------------- CSR build ----------------
__global__ __launch_bounds__(256)
void zerodeg_k()
{
    int i = blockIdx.x * 256 + threadIdx.x;
    if (i < NN) g_deg[i] = 0;
}

__global__ __launch_bounds__(256)
void hist_k(const int* __restrict__ ei)
{
    int e = blockIdx.x * 256 + threadIdx.x;
    if (e < EE) atomicAdd(&g_deg[ei[EE + e]], 1);
}

__global__ __launch_bounds__(1024)
void scan_k()
{
    __shared__ int s[1024];
    __shared__ int carry_s;
    int tid = threadIdx.x;
    if (tid == 0) carry_s = 0;
    __syncthreads();
    for (int base = 0; base < NN; base += 4096) {
        int i0 = base + tid * 4;
        int v0 = (i0 + 0 < NN) ? g_deg[i0 + 0] : 0;
        int v1 = (i0 + 1 < NN) ? g_deg[i0 + 1] : 0;
        int v2 = (i0 + 2 < NN) ? g_deg[i0 + 2] : 0;
        int v3 = (i0 + 3 < NN) ? g_deg[i0 + 3] : 0;
        int tsum = v0 + v1 + v2 + v3;
        int val = tsum;
        s[tid] = val;
        __syncthreads();
        #pragma unroll
        for (int off = 1; off < 1024; off <<= 1) {
            int t = (tid >= off) ? s[tid - off] : 0;
            __syncthreads();
            val += t;
            s[tid] = val;
            __syncthreads();
        }
        int carry = carry_s;
        int o0 = carry + val - tsum;
        int o1 = o0 + v0, o2 = o1 + v1, o3 = o2 + v2;
        if (i0 + 0 < NN) { g_off[i0 + 0] = o0; g_pos[i0 + 0] = o0; }
        if (i0 + 1 < NN) { g_off[i0 + 1] = o1; g_pos[i0 + 1] = o1; }
        if (i0 + 2 < NN) { g_off[i0 + 2] = o2; g_pos[i0 + 2] = o2; }
        if (i0 + 3 < NN) { g_off[i0 + 3] = o3; g_pos[i0 + 3] = o3; }
        __syncthreads();
        if (tid == 1023) carry_s = carry + val;
        __syncthreads();
    }
    if (tid == 0) g_off[NN] = EE;
}

__global__ __launch_bounds__(256)
void fill_k(const int* __restrict__ ei, const int* __restrict__ et)
{
    int e = blockIdx.x * 256 + threadIdx.x;
    if (e >= EE) return;
    int dst = ei[EE + e];
    int p = atomicAdd(&g_pos[dst], 1);
    g_csrc[p] = (ei[e] << 3) | et[e];
    g_cdst[p] = dst;
}

// ---------------- attention projections ----------------
__global__ __launch_bounds__(256)
void attproj_k(const float* __restrict__ h, const float* __restrict__ W_att)
{
    __shared__ float hs[16][65];
    __shared__ float ws[16][65];
    int tid = threadIdx.x;
    int nodeBase = blockIdx.x * 16;
    for (int i = tid; i < 16 * 64; i += 256) {
        int o = i >> 6, c = i & 63;
        ws[o][c] = W_att[(o & 7) * 128 + ((o >> 3) << 6) + c];
        int n = nodeBase + o;
        hs[o][c] = (n < NN) ? h[n * 64 + c] : 0.f;
    }
    __syncthreads();
    int nd = tid >> 4, o = tid & 15;
    float s = 0.f;
    #pragma unroll
    for (int c = 0; c < 64; c++) s += hs[nd][c] * ws[o][c];
    int n = nodeBase + nd;
    if (n < NN) g_ap[n * 16 + o] = s;
    if (blockIdx.x == 0 && tid < RR) g_denom[tid] = 0.f;
}

// ---------------- scores + exp + denom, CSR order ----------
__global__ __launch_bounds__(256)
void scoreexp_k(const float* __restrict__ b_att)
{
    __shared__ float ssum[RR];
    int tid = threadIdx.x;
    if (tid < RR) ssum[tid] = 0.f;
    __syncthreads();
    int j = blockIdx.x * 256 + tid;
    if (j < EE) {
        int pk = g_csrc[j];
        int t = pk & 7;
        int s = pk >> 3;
        int d = g_cdst[j];
        float sc = g_ap[s * 16 + t] + g_ap[d * 16 + 8 + t] + b_att[t];
        sc = (sc > 0.f) ? sc : NEG_SLOPE * sc;
        float ex = __expf(sc);
        g_exc[j] = ex;
        atomicAdd(&ssum[t], ex);
    }
    __syncthreads();
    if (tid < RR) atomicAdd(&g_denom[tid], ssum[tid]);
}

// ---------------- aggregate att-weighted h16[src] per (dst, r) ----------------
// warp per node, half-warp per edge, 8B fp16 gathers (one line per edge row).
__global__ __launch_bounds__(256)
void aggscatter_k(const __half* __restrict__ h16)
{
    __shared__ float sden[RR];
    int tid = threadIdx.x;
    if (tid < RR) sden[tid] = 1.f / g_denom[tid];
    __syncthreads();

    int warp = tid >> 5, lane = tid & 31;
    int half = lane >> 4;
    int c4 = (lane & 15) * 4;
    int n = blockIdx.x * 8 + warp;
    if (n >= NN) return;

    float4 acc[8];
    #pragma unroll
    for (int r = 0; r < 8; r++) acc[r] = make_float4(0.f, 0.f, 0.f, 0.f);

    int beg = g_off[n], end = g_off[n + 1];
    for (int b = beg; b < end; b += 8) {
        int pk[4]; float at[4];
        #pragma unroll
        for (int i = 0; i < 4; i++) {
            int j = b + 2 * i + half;
            int jc = (j < end) ? j : beg;
            pk[i] = g_csrc[jc];
            float ex = g_exc[jc];
            at[i] = (j < end) ? ex * sden[pk[i] & 7] : 0.f;
        }
        uint2 u[4];
        #pragma unroll
        for (int i = 0; i < 4; i++)
            u[i] = *reinterpret_cast<const uint2*>(&h16[(size_t)(pk[i] >> 3) * 64 + c4]);
        #pragma unroll
        for (int i = 0; i < 4; i++) {
            float2 v01 = __half22float2(*reinterpret_cast<__half2*>(&u[i].x));
            float2 v23 = __half22float2(*reinterpret_cast<__half2*>(&u[i].y));
            int er = pk[i] & 7;
            #pragma unroll
            for (int r = 0; r < 8; r++)
                if (er == r) {
                    acc[r].x += at[i] * v01.x; acc[r].y += at[i] * v01.y;
                    acc[r].z += at[i] * v23.x; acc[r].w += at[i] * v23.y;
                }
        }
    }

    #pragma unroll
    for (int r = 0; r < 8; r++) {
        acc[r].x += __shfl_xor_sync(0xffffffffu, acc[r].x, 16);
        acc[r].y += __shfl_xor_sync(0xffffffffu, acc[r].y, 16);
        acc[r].z += __shfl_xor_sync(0xffffffffu, acc[r].z, 16);
        acc[r].w += __shfl_xor_sync(0xffffffffu, acc[r].w, 16);
    }

    if (half == 0) {
        size_t base = (size_t)n * 512;
        #pragma unroll
        for (int r = 0; r < 8; r++) {
            __half2 p0 = __floats2half2_rn(acc[r].x, acc[r].y);
            __half2 p1 = __floats2half2_rn(acc[r].z, acc[r].w);
            uint2 u;
            u.x = *reinterpret_cast<uint32_t*>(&p0);
            u.y = *reinterpret_cast<uint32_t*>(&p1);
            *reinterpret_cast<uint2*>(&g_spre[base + r * 64 + c4]) = u;
        }
    }
}

// ---------------- gate*prod mean + residual + LN + relu (fp16 gate/prod) ----
// writes fp32 hout and fp16 mirror h16out.
__global__ __launch_bounds__(256)
void combine_k(const float* __restrict__ hin, float* __restrict__ hout,
               __half* __restrict__ h16out,
               const float* __restrict__ b_gate,
               const float* __restrict__ gamma, const float* __restrict__ beta)
{
    int tid = threadIdx.x;
    int warp = tid >> 5, lane = tid & 31;
    int half = lane >> 4;
    int c4 = (lane & 15) * 4;
    int n = blockIdx.x * 8 + warp;
    if (n >= NN) return;

    size_t base = (size_t)n * 512;
    float4 hx = make_float4(0.f, 0.f, 0.f, 0.f);
    #pragma unroll
    for (int rr = 0; rr < 4; rr++) {
        int r = 2 * rr + half;
        int o = r * 64 + c4;
        uint2 gu = *reinterpret_cast<const uint2*>(&g_gate[base + o]);
        uint2 pu = *reinterpret_cast<const uint2*>(&g_prod[base + o]);
        float2 g01 = __half22float2(*reinterpret_cast<__half2*>(&gu.x));
        float2 g23 = __half22float2(*reinterpret_cast<__half2*>(&gu.y));
        float2 p01 = __half22float2(*reinterpret_cast<__half2*>(&pu.x));
        float2 p23 = __half22float2(*reinterpret_cast<__half2*>(&pu.y));
        float4 bg = *reinterpret_cast<const float4*>(&b_gate[o]);
        hx.x += p01.x / (1.f + __expf(-(g01.x + bg.x)));
        hx.y += p01.y / (1.f + __expf(-(g01.y + bg.y)));
        hx.z += p23.x / (1.f + __expf(-(g23.x + bg.z)));
        hx.w += p23.y / (1.f + __expf(-(g23.y + bg.w)));
    }
    hx.x += __shfl_xor_sync(0xffffffffu, hx.x, 16);
    hx.y += __shfl_xor_sync(0xffffffffu, hx.y, 16);
    hx.z += __shfl_xor_sync(0xffffffffu, hx.z, 16);
    hx.w += __shfl_xor_sync(0xffffffffu, hx.w, 16);

    float4 hv = *reinterpret_cast<const float4*>(&hin[(size_t)n * 64 + c4]);
    float h0 = hv.x + hx.x * 0.125f;
    float h1 = hv.y + hx.y * 0.125f;
    float h2 = hv.z + hx.z * 0.125f;
    float h3 = hv.w + hx.w * 0.125f;

    float s = h0 + h1 + h2 + h3;
    #pragma unroll
    for (int o = 8; o > 0; o >>= 1) s += __shfl_xor_sync(0xffffffffu, s, o);
    float mu = s * (1.f / 64.f);
    float d0 = h0 - mu, d1 = h1 - mu, d2 = h2 - mu, d3 = h3 - mu;
    float v = d0 * d0 + d1 * d1 + d2 * d2 + d3 * d3;
    #pragma unroll
    for (int o = 8; o > 0; o >>= 1) v += __shfl_xor_sync(0xffffffffu, v, o);
    float rs = rsqrtf(v * (1.f / 64.f) + LN_EPS);

    if (half == 0) {
        float4 gm = *reinterpret_cast<const float4*>(&gamma[c4]);
        float4 bt = *reinterpret_cast<const float4*>(&beta[c4]);
        float4 o4;
        o4.x = fmaxf(d0 * rs * gm.x + bt.x, 0.f);
        o4.y = fmaxf(d1 * rs * gm.y + bt.y, 0.f);
        o4.z = fmaxf(d2 * rs * gm.z + bt.z, 0.f);
        o4.w = fmaxf(d3 * rs * gm.w + bt.w, 0.f);
        *reinterpret_cast<float4*>(&hout[(size_t)n * 64 + c4]) = o4;
        __half2 m0 = __floats2half2_rn(o4.x, o4.y);
        __half2 m1 = __floats2half2_rn(o4.z, o4.w);
        uint2 mu2;
        mu2.x = *reinterpret_cast<uint32_t*>(&m0);
        mu2.y = *reinterpret_cast<uint32_t*>(&m1);
        *reinterpret_cast<uint2*>(&h16out[(size_t)n * 64 + c4]) = mu2;
    }
}

// ---------------- launch ----------------
extern "C" void kernel_launch(void* const* d_in, const int* in_sizes, int n_in,
                              void* d_out, int out_size)
{
    const float* x      = (const float*)d_in[0];
    const int*   ei     = (const int*)  d_in[1];
    const int*   et     = (const int*)  d_in[2];
    const float* W_in   = (const float*)d_in[3];
    const float* b_in   = (const float*)d_in[4];
    const float* W_rel  = (const float*)d_in[5];
    const float* W_gate = (const float*)d_in[6];
    const float* b_gate = (const float*)d_in[7];
    const float* W_att  = (const float*)d_in[8];
    const float* b_att  = (const float*)d_in[9];
    const float* ln_g   = (const float*)d_in[10];
    const float* ln_b   = (const float*)d_in[11];
    const float* W_out  = (const float*)d_in[12];
    const float* b_out  = (const float*)d_in[13];
    float* out = (float*)d_out;

    float* hbuf;
    __half* h16buf;
    void *sprep, *gatep, *prodp;
    cudaGetSymbolAddress((void**)&hbuf, g_h);
    cudaGetSymbolAddress((void**)&h16buf, g_h16);
    cudaGetSymbolAddress(&sprep, g_spre);
    cudaGetSymbolAddress(&gatep, g_gate);
    cudaGetSymbolAddress(&prodp, g_prod);
    float* h0p = hbuf;
    float* h1p = hbuf + (size_t)NN * HH;
    __half* h16_0 = h16buf;
    __half* h16_1 = h16buf + (size_t)NN * HH;

    cudaFuncSetAttribute(gemm64k, cudaFuncAttributeMaxDynamicSharedMemorySize, GEMM_SMEM);
    cudaFuncSetAttribute(gemmbf,  cudaFuncAttributeMaxDynamicSharedMemorySize, GEMMBF_SMEM);

    static cudaStream_t s2 = nullptr;
    static cudaEvent_t evF = nullptr, evG = nullptr, evC = nullptr;
    if (!s2) {
        cudaStreamCreateWithFlags(&s2, cudaStreamNonBlocking);
        cudaEventCreateWithFlags(&evF, cudaEventDisableTiming);
        cudaEventCreateWithFlags(&evG, cudaEventDisableTiming);
        cudaEventCreateWithFlags(&evC, cudaEventDisableTiming);
    }

    // fork: CSR build on s2, input projection on main
    cudaEventRecord(evF, 0);
    cudaStreamWaitEvent(s2, evF, 0);
    zerodeg_k<<<(NN + 255) / 256, 256, 0, s2>>>();
    hist_k<<<(EE + 255) / 256, 256, 0, s2>>>(ei);
    scan_k<<<1, 1024, 0, s2>>>();
    fill_k<<<(EE + 255) / 256, 256, 0, s2>>>(ei, et);
    cudaEventRecord(evC, s2);

    // input projection (writes fp32 h0 + fp16 mirror)
    gemm64k<<<dim3((NN + 127) / 128, 1), 128, GEMM_SMEM>>>(x, 64, W_in, b_in, h0p, 64, NN, 0, 1, h16_0);

    float* hc = h0p;      float* hn = h1p;
    __half* hc16 = h16_0; __half* hn16 = h16_1;
    for (int layer = 0; layer < LL; layer++) {
        // fork: gate GEMM (bf16 split, fp16 out) on s2
        cudaEventRecord(evF, 0);
        cudaStreamWaitEvent(s2, evF, 0);
        gemmbf<<<dim3((NN + 127) / 128, 8), 128, GEMMBF_SMEM, s2>>>(hc, 64, W_gate, nullptr, gatep, 512, NN, 0, 0, 1, 0);
        cudaEventRecord(evG, s2);

        // main: edge chain
        attproj_k<<<(NN + 15) / 16, 256>>>(hc, W_att);
        if (layer == 0) cudaStreamWaitEvent(0, evC, 0);
        scoreexp_k<<<(EE + 255) / 256, 256>>>(b_att);
        aggscatter_k<<<(NN + 7) / 8, 256>>>(hc16);
        gemmbf<<<dim3((NN + 127) / 128, 8), 128, GEMMBF_SMEM>>>(sprep, 512, W_rel, nullptr, prodp, 512, NN, 1, 0, 1, 1);

        cudaStreamWaitEvent(0, evG, 0);
        combine_k<<<(NN + 7) / 8, 256>>>(hc, hn, hn16, b_gate, ln_g + layer * 64, ln_b + layer * 64);
        float* tf = hc; hc = hn; hn = tf;
        __half* th = hc16; hc16 = hn16; hn16 = th;
    }

    gemm64k<<<dim3((NN + 127) / 128, 1), 128, GEMM_SMEM>>>(hc, 64, W_out, b_out, out, 64, NN, 0, 0, nullptr);
}